// round 14
// baseline (speedup 1.0000x reference)
#include <cuda_runtime.h>
#include <cuda_bf16.h>
#include <cuda_fp16.h>
#include <math.h>
#include <stdint.h>

#define CCH   512
#define TT    8
#define HWN   4096
#define PN    (TT*HWN)
#define GROUPS 32
#define GSIZE (16*PN)

// ---------------- scratch (device globals) ----------------------------------
__device__ float g_mean[GROUPS];
__device__ float g_rstd[GROUPS];
__device__ __nv_bfloat16 g_hl[(size_t)PN * CCH];
__device__ uint8_t       g_q8[(size_t)PN * CCH];
__device__ uint8_t       g_k8[(size_t)PN * CCH];
__device__ __nv_bfloat16 g_v [(size_t)PN * CCH];
__device__ uint8_t       g_vt8[(size_t)PN * CCH];
__device__ __nv_bfloat16 g_o [(size_t)PN * CCH];
__device__ uint8_t       g_P8[(size_t)TT * HWN * HWN];   // 128 MB: 16*exp(logit) e4m3
__device__ float         g_rsum[(size_t)TT * HWN];       // per-row sums of P8
__device__ __nv_bfloat16 g_wt[4 * CCH * CCH];

struct Ptr3 {
    const float* b0; const float* b1; const float* b2;
    void* o0; void* o1; void* o2;
};
struct W4 { const float* w[4]; };

// ---------------- PTX helpers -------------------------------------------------
__device__ __forceinline__ uint32_t smem_u32(const void* p) {
    uint32_t a;
    asm("{ .reg .u64 t; cvta.to.shared.u64 t, %1; cvt.u32.u64 %0, t; }" : "=r"(a) : "l"(p));
    return a;
}
__device__ __forceinline__ void ldsm_x4(uint32_t& r0, uint32_t& r1, uint32_t& r2,
                                        uint32_t& r3, uint32_t addr) {
    asm volatile("ldmatrix.sync.aligned.m8n8.x4.shared.b16 {%0,%1,%2,%3}, [%4];"
                 : "=r"(r0), "=r"(r1), "=r"(r2), "=r"(r3) : "r"(addr));
}
__device__ __forceinline__ void mma16816(float* d, const uint32_t* a, const uint32_t* b) {
    asm volatile("mma.sync.aligned.m16n8k16.row.col.f32.bf16.bf16.f32 "
                 "{%0,%1,%2,%3}, {%4,%5,%6,%7}, {%8,%9}, {%0,%1,%2,%3};"
                 : "+f"(d[0]), "+f"(d[1]), "+f"(d[2]), "+f"(d[3])
                 : "r"(a[0]), "r"(a[1]), "r"(a[2]), "r"(a[3]), "r"(b[0]), "r"(b[1]));
}
__device__ __forceinline__ void mma16832(float* d, const uint32_t* a, const uint32_t* b) {
    asm volatile("mma.sync.aligned.m16n8k32.row.col.f32.e4m3.e4m3.f32 "
                 "{%0,%1,%2,%3}, {%4,%5,%6,%7}, {%8,%9}, {%0,%1,%2,%3};"
                 : "+f"(d[0]), "+f"(d[1]), "+f"(d[2]), "+f"(d[3])
                 : "r"(a[0]), "r"(a[1]), "r"(a[2]), "r"(a[3]), "r"(b[0]), "r"(b[1]));
}
__device__ __forceinline__ void cp16(uint32_t sm, const void* gp) {
    asm volatile("cp.async.cg.shared.global [%0], [%1], 16;" :: "r"(sm), "l"(gp) : "memory");
}
#define CP_COMMIT() asm volatile("cp.async.commit_group;" ::: "memory")
template<int W> __device__ __forceinline__ void cp_wait() {
    asm volatile("cp.async.wait_group %0;" :: "n"(W) : "memory");
}
// packed fp8 convert: lower byte = lo, upper = hi
__device__ __forceinline__ uint16_t fp8x2(float lo, float hi) {
    uint16_t r;
    asm("cvt.rn.satfinite.e4m3x2.f32 %0, %1, %2;" : "=h"(r) : "f"(hi), "f"(lo));
    return r;
}
// e4m3x2 -> float2
__device__ __forceinline__ float2 e4m3x2_f2(uint16_t h) {
    uint32_t f16x2;
    asm("cvt.rn.f16x2.e4m3x2 %0, %1;" : "=r"(f16x2) : "h"(h));
    return __half22float2(*(__half2*)&f16x2);
}

// FMA-only exp
__device__ __forceinline__ float fexp(float x) {
    float y = fmaxf(x * 1.44269504f, -120.f);
    float n = rintf(y);
    float f = y - n;
    float p = 0.00133336f;
    p = fmaf(p, f, 0.00961813f);
    p = fmaf(p, f, 0.05550411f);
    p = fmaf(p, f, 0.24022651f);
    p = fmaf(p, f, 0.69314718f);
    p = fmaf(p, f, 1.0f);
    return __int_as_float(__float_as_int(p) + (((int)n) << 23));
}

// ---------------- group-norm stats --------------------------------------------
__global__ void __launch_bounds__(512) gn_stats(const float* __restrict__ x) {
    int g = blockIdx.x;
    const float4* p = (const float4*)(x + (size_t)g * GSIZE);
    float s = 0.f, ss = 0.f;
    for (int i = threadIdx.x; i < GSIZE / 4; i += 512) {
        float4 v = p[i];
        s  += v.x + v.y + v.z + v.w;
        ss += v.x * v.x + v.y * v.y + v.z * v.z + v.w * v.w;
    }
    __shared__ float shs[512], shq[512];
    shs[threadIdx.x] = s; shq[threadIdx.x] = ss;
    __syncthreads();
    for (int st = 256; st > 0; st >>= 1) {
        if (threadIdx.x < st) {
            shs[threadIdx.x] += shs[threadIdx.x + st];
            shq[threadIdx.x] += shq[threadIdx.x + st];
        }
        __syncthreads();
    }
    if (threadIdx.x == 0) {
        float m = shs[0] / (float)GSIZE;
        float var = shq[0] / (float)GSIZE - m * m;
        g_mean[g] = m;
        g_rstd[g] = rsqrtf(var + 1e-6f);
    }
}

// ---------------- normalize + transpose to channels-last (bf16) ---------------
__global__ void __launch_bounds__(1024) norm_transpose(
    const float* __restrict__ x, const float* __restrict__ gamma,
    const float* __restrict__ beta, __nv_bfloat16* __restrict__ hl)
{
    __shared__ float tile[32][33];
    int p0 = blockIdx.x * 32, c0 = blockIdx.y * 32;
    int c = c0 + threadIdx.y;
    tile[threadIdx.y][threadIdx.x] = x[(size_t)c * PN + p0 + threadIdx.x];
    __syncthreads();
    int cc = c0 + threadIdx.x;
    int g = cc >> 4;
    float a = gamma[cc] * g_rstd[g];
    float b = beta[cc] - g_mean[g] * a;
    hl[(size_t)(p0 + threadIdx.y) * CCH + cc] =
        __float2bfloat16(tile[threadIdx.x][threadIdx.y] * a + b);
}

// ---------------- batched weight transpose fp32 [K][N] -> bf16 [N][K] ----------
__global__ void __launch_bounds__(1024) wtrans4(W4 ws, __nv_bfloat16* __restrict__ Wt)
{
    __shared__ float t[32][33];
    const float* W = ws.w[blockIdx.z];
    __nv_bfloat16* Wo = Wt + (size_t)blockIdx.z * CCH * CCH;
    int k0 = blockIdx.y * 32, n0 = blockIdx.x * 32;
    t[threadIdx.y][threadIdx.x] = W[(size_t)(k0 + threadIdx.y) * CCH + n0 + threadIdx.x];
    __syncthreads();
    Wo[(size_t)(n0 + threadIdx.y) * CCH + k0 + threadIdx.x] =
        __float2bfloat16(t[threadIdx.x][threadIdx.y]);
}

// ---------------- V transpose bf16 [t*4096+p][c] -> fp8 [t][c][p] ---------------
__global__ void __launch_bounds__(1024) vtrans8(const __nv_bfloat16* __restrict__ v,
                                                uint8_t* __restrict__ vt8)
{
    __shared__ __nv_bfloat16 t[32][33];
    int ts = blockIdx.z, p0 = blockIdx.x * 32, c0 = blockIdx.y * 32;
    t[threadIdx.y][threadIdx.x] =
        v[(size_t)(ts * HWN + p0 + threadIdx.y) * CCH + c0 + threadIdx.x];
    __syncthreads();
    float val = __bfloat162float(t[threadIdx.x][threadIdx.y]);
    uint16_t pk = fp8x2(val, 0.f);
    vt8[(size_t)ts * CCH * HWN + (size_t)(c0 + threadIdx.y) * HWN + p0 + threadIdx.x] =
        (uint8_t)(pk & 0xFF);
}

// =================== bf16 GEMM 128x128xBK64 (R6 geometry, 2 CTAs/SM) ============
#define BK   64
#define ROWB 144
#define BM 128
#define BN 128
#define HSTG (BM * ROWB)          // 18432
#define STG  (2 * HSTG)           // 36864
#define SMEM_PIPE (3 * STG)       // 110592

__device__ __forceinline__ void load_tile64(uint32_t sm_base, const __nv_bfloat16* g,
                                            int ld, int row0, int k0, int tid)
{
    #pragma unroll
    for (int i = 0; i < 4; ++i) {
        int id  = i * 256 + tid;
        int row = id >> 3;
        int ch  = id & 7;
        cp16(sm_base + row * ROWB + ch * 16, g + (size_t)(row0 + row) * ld + k0 + ch * 8);
    }
}

__global__ void __launch_bounds__(256, 2) gemm_qkv(
    const __nv_bfloat16* __restrict__ A, const __nv_bfloat16* __restrict__ B,
    int N, int K, Ptr3 p3)
{
    extern __shared__ __nv_bfloat16 smem[];
    const uint32_t sb = smem_u32(smem);
    const int tid = threadIdx.x, wid = tid >> 5, lane = tid & 31;
    const int m0 = blockIdx.y * BM, n0 = blockIdx.x * BN;
    const int z = blockIdx.z;

    B += (size_t)z * (CCH * CCH);
    const float* bias_p = (z == 0) ? p3.b0 : (z == 1) ? p3.b1 : p3.b2;
    void* outp          = (z == 0) ? p3.o0 : (z == 1) ? p3.o1 : p3.o2;

    const int wm = wid & 3, wn = wid >> 2;
    const int wrow = wm * 32, wcol = wn * 64;
    const int KT = K / BK;

    uint32_t a_off[2];
    #pragma unroll
    for (int mt = 0; mt < 2; ++mt)
        a_off[mt] = (wrow + mt * 16 + (lane & 15)) * ROWB + ((lane >> 4) << 4);
    uint32_t b_off[4];
    #pragma unroll
    for (int np = 0; np < 4; ++np) {
        int n  = wcol + np * 16 + (lane & 7) + ((lane >> 4) << 3);
        int kf = ((lane >> 3) & 1) << 3;
        b_off[np] = n * ROWB + kf * 2;
    }

    float acc[2][8][4];
    #pragma unroll
    for (int i = 0; i < 2; ++i)
        #pragma unroll
        for (int j = 0; j < 8; ++j)
            #pragma unroll
            for (int q = 0; q < 4; ++q) acc[i][j][q] = 0.f;

    #pragma unroll
    for (int s = 0; s < 2; ++s) {
        load_tile64(sb + s * STG, A, K, m0, s * BK, tid);
        load_tile64(sb + s * STG + HSTG, B, K, n0, s * BK, tid);
        CP_COMMIT();
    }

    for (int it = 0; it < KT; ++it) {
        cp_wait<1>();
        __syncthreads();
        if (it + 2 < KT) {
            int s = (it + 2) % 3;
            load_tile64(sb + s * STG, A, K, m0, (it + 2) * BK, tid);
            load_tile64(sb + s * STG + HSTG, B, K, n0, (it + 2) * BK, tid);
        }
        CP_COMMIT();

        const uint32_t as = sb + (it % 3) * STG;
        const uint32_t bs = as + HSTG;
        #pragma unroll
        for (int kk = 0; kk < 4; ++kk) {
            uint32_t a[2][4], b[8][2];
            #pragma unroll
            for (int mt = 0; mt < 2; ++mt)
                ldsm_x4(a[mt][0], a[mt][1], a[mt][2], a[mt][3], as + a_off[mt] + kk * 32);
            #pragma unroll
            for (int np = 0; np < 4; ++np)
                ldsm_x4(b[np*2][0], b[np*2][1], b[np*2+1][0], b[np*2+1][1],
                        bs + b_off[np] + kk * 32);
            #pragma unroll
            for (int mt = 0; mt < 2; ++mt)
                #pragma unroll
                for (int nt = 0; nt < 8; ++nt)
                    mma16816(acc[mt][nt], a[mt], b[nt]);
        }
    }

    const int r_lane = lane >> 2, c_lane = (lane & 3) * 2;
    const bool f8out = (z != 2);
    #pragma unroll
    for (int mt = 0; mt < 2; ++mt) {
        int r0 = m0 + wrow + mt * 16 + r_lane;
        #pragma unroll
        for (int nt = 0; nt < 8; ++nt) {
            int c = n0 + wcol + nt * 8 + c_lane;
            float b0 = bias_p[c], b1 = bias_p[c + 1];
            float v0 = acc[mt][nt][0] + b0, v1 = acc[mt][nt][1] + b1;
            float v2 = acc[mt][nt][2] + b0, v3 = acc[mt][nt][3] + b1;
            if (f8out) {
                uint8_t* Cb = (uint8_t*)outp;
                *(uint16_t*)(Cb + (size_t)r0 * N + c)       = fp8x2(v0, v1);
                *(uint16_t*)(Cb + (size_t)(r0 + 8) * N + c) = fp8x2(v2, v3);
            } else {
                __nv_bfloat16* Cb = (__nv_bfloat16*)outp;
                *(__nv_bfloat162*)(Cb + (size_t)r0 * N + c)       = __floats2bfloat162_rn(v0, v1);
                *(__nv_bfloat162*)(Cb + (size_t)(r0 + 8) * N + c) = __floats2bfloat162_rn(v2, v3);
            }
        }
    }
}

// ============ FP8 GEMM 128x128xBK64 e4m3, 3 stages, 2 CTAs/SM (R9 core) =========
// EXPOUT=1: C=fp8( 16*exp(scale*acc) )  [QK->P8, no softmax pass needed]
// EXPOUT=0: C=bf16( acc / rsum[row] )   [PV with fused per-row normalization]
#define ROWB8 80
#define HSTG8 (BM * ROWB8)        // 10240
#define STG8  (2 * HSTG8)         // 20480
#define SMEM_PIPE8 (3 * STG8)     // 61440

__device__ __forceinline__ void load_tile8(uint32_t sm_base, const uint8_t* g,
                                           int ld, int row0, int k0, int tid)
{
    #pragma unroll
    for (int i = 0; i < 2; ++i) {
        int id  = i * 256 + tid;
        int row = id >> 2;
        int ch  = id & 3;
        cp16(sm_base + row * ROWB8 + ch * 16, g + (size_t)(row0 + row) * ld + k0 + ch * 16);
    }
}

template<int EXPOUT>
__global__ void __launch_bounds__(256, 2) gemm_fp8(
    const uint8_t* __restrict__ A, const uint8_t* __restrict__ B,
    void* __restrict__ Cout, const float* __restrict__ rsum,
    int N, int K, float scale, size_t sA, size_t sB, size_t sC)
{
    extern __shared__ __nv_bfloat16 smem[];
    const uint32_t sb = smem_u32(smem);
    const int tid = threadIdx.x, wid = tid >> 5, lane = tid & 31;
    const int m0 = blockIdx.y * BM, n0 = blockIdx.x * BN;
    const int z = blockIdx.z;
    A += (size_t)z * sA;
    B += (size_t)z * sB;

    const int wm = wid & 3, wn = wid >> 2;
    const int wrow = wm * 32, wcol = wn * 64;
    const int KT = K / BK;

    uint32_t a_off[2];
    #pragma unroll
    for (int mt = 0; mt < 2; ++mt)
        a_off[mt] = (wrow + mt * 16 + (lane & 15)) * ROWB8 + ((lane >> 4) << 4);
    uint32_t b_off[4];
    #pragma unroll
    for (int np = 0; np < 4; ++np) {
        int n = wcol + np * 16 + (lane & 7) + ((lane >> 4) << 3);
        b_off[np] = n * ROWB8 + (((lane >> 3) & 1) << 4);
    }

    float acc[2][8][4];
    #pragma unroll
    for (int i = 0; i < 2; ++i)
        #pragma unroll
        for (int j = 0; j < 8; ++j)
            #pragma unroll
            for (int q = 0; q < 4; ++q) acc[i][j][q] = 0.f;

    #pragma unroll
    for (int s = 0; s < 2; ++s) {
        load_tile8(sb + s * STG8, A, K, m0, s * BK, tid);
        load_tile8(sb + s * STG8 + HSTG8, B, K, n0, s * BK, tid);
        CP_COMMIT();
    }

    for (int it = 0; it < KT; ++it) {
        cp_wait<1>();
        __syncthreads();
        if (it + 2 < KT) {
            int s = (it + 2) % 3;
            load_tile8(sb + s * STG8, A, K, m0, (it + 2) * BK, tid);
            load_tile8(sb + s * STG8 + HSTG8, B, K, n0, (it + 2) * BK, tid);
        }
        CP_COMMIT();

        const uint32_t as = sb + (it % 3) * STG8;
        const uint32_t bs = as + HSTG8;
        #pragma unroll
        for (int kk = 0; kk < 2; ++kk) {     // 2 x k32 per BK64
            uint32_t a[2][4], b[8][2];
            #pragma unroll
            for (int mt = 0; mt < 2; ++mt)
                ldsm_x4(a[mt][0], a[mt][1], a[mt][2], a[mt][3], as + a_off[mt] + kk * 32);
            #pragma unroll
            for (int np = 0; np < 4; ++np)
                ldsm_x4(b[np*2][0], b[np*2][1], b[np*2+1][0], b[np*2+1][1],
                        bs + b_off[np] + kk * 32);
            #pragma unroll
            for (int mt = 0; mt < 2; ++mt)
                #pragma unroll
                for (int nt = 0; nt < 8; ++nt)
                    mma16832(acc[mt][nt], a[mt], b[nt]);
        }
    }

    const int r_lane = lane >> 2, c_lane = (lane & 3) * 2;
    #pragma unroll
    for (int mt = 0; mt < 2; ++mt) {
        int r0 = m0 + wrow + mt * 16 + r_lane;
        if (EXPOUT) {
            uint8_t* C8 = (uint8_t*)Cout + (size_t)z * sC;
            #pragma unroll
            for (int nt = 0; nt < 8; ++nt) {
                int c = n0 + wcol + nt * 8 + c_lane;
                float e0 = 16.f * fexp(acc[mt][nt][0] * scale);
                float e1 = 16.f * fexp(acc[mt][nt][1] * scale);
                float e2 = 16.f * fexp(acc[mt][nt][2] * scale);
                float e3 = 16.f * fexp(acc[mt][nt][3] * scale);
                *(uint16_t*)(C8 + (size_t)r0 * N + c)       = fp8x2(e0, e1);
                *(uint16_t*)(C8 + (size_t)(r0 + 8) * N + c) = fp8x2(e2, e3);
            }
        } else {
            __nv_bfloat16* C = (__nv_bfloat16*)Cout + (size_t)z * sC;
            float fa = 1.f / rsum[(size_t)z * HWN + r0];
            float fb = 1.f / rsum[(size_t)z * HWN + r0 + 8];
            #pragma unroll
            for (int nt = 0; nt < 8; ++nt) {
                int c = n0 + wcol + nt * 8 + c_lane;
                *(__nv_bfloat162*)(C + (size_t)r0 * N + c) =
                    __floats2bfloat162_rn(acc[mt][nt][0] * fa, acc[mt][nt][1] * fa);
                *(__nv_bfloat162*)(C + (size_t)(r0 + 8) * N + c) =
                    __floats2bfloat162_rn(acc[mt][nt][2] * fb, acc[mt][nt][3] * fb);
            }
        }
    }
}

// ---------------- row sums of P8 (e4m3), one block per row ----------------------
__global__ void __launch_bounds__(256) rowsum8(const uint8_t* __restrict__ P8,
                                               float* __restrict__ rsum)
{
    __shared__ float red[8];
    const uint4* p = (const uint4*)(P8 + (size_t)blockIdx.x * HWN);
    uint4 d = p[threadIdx.x];              // 16 fp8 values per thread
    float s = 0.f;
    const uint16_t* h = (const uint16_t*)&d;
    #pragma unroll
    for (int i = 0; i < 8; ++i) {
        float2 t = e4m3x2_f2(h[i]);
        s += t.x + t.y;
    }
    #pragma unroll
    for (int o = 16; o > 0; o >>= 1) s += __shfl_xor_sync(0xffffffffu, s, o);
    int wid = threadIdx.x >> 5, lane = threadIdx.x & 31;
    if (lane == 0) red[wid] = s;
    __syncthreads();
    if (wid == 0) {
        float t = (lane < 8) ? red[lane] : 0.f;
        #pragma unroll
        for (int o = 16; o > 0; o >>= 1) t += __shfl_xor_sync(0xffffffffu, t, o);
        if (lane == 0) rsum[blockIdx.x] = t;
    }
}

// =================== 128x128xBK64 bf16 GEMM with fused transpose+residual =======
__global__ void __launch_bounds__(256, 2) gemm_transadd(
    const __nv_bfloat16* __restrict__ A, const __nv_bfloat16* __restrict__ B,
    const float* __restrict__ bias, float* __restrict__ Cout,
    int K, const float* __restrict__ xres)
{
    extern __shared__ __nv_bfloat16 smem[];
    const uint32_t sb = smem_u32(smem);
    const int tid = threadIdx.x, wid = tid >> 5, lane = tid & 31;
    const int m0 = blockIdx.y * BM, n0 = blockIdx.x * BN;

    const int wm = wid & 3, wn = wid >> 2;
    const int wrow = wm * 32, wcol = wn * 64;
    const int KT = K / BK;

    uint32_t a_off[2];
    #pragma unroll
    for (int mt = 0; mt < 2; ++mt)
        a_off[mt] = (wrow + mt * 16 + (lane & 15)) * ROWB + ((lane >> 4) << 4);
    uint32_t b_off[4];
    #pragma unroll
    for (int np = 0; np < 4; ++np) {
        int n  = wcol + np * 16 + (lane & 7) + ((lane >> 4) << 3);
        int kf = ((lane >> 3) & 1) << 3;
        b_off[np] = n * ROWB + kf * 2;
    }

    float acc[2][8][4];
    #pragma unroll
    for (int i = 0; i < 2; ++i)
        #pragma unroll
        for (int j = 0; j < 8; ++j)
            #pragma unroll
            for (int q = 0; q < 4; ++q) acc[i][j][q] = 0.f;

    #pragma unroll
    for (int s = 0; s < 2; ++s) {
        load_tile64(sb + s * STG, A, K, m0, s * BK, tid);
        load_tile64(sb + s * STG + HSTG, B, K, n0, s * BK, tid);
        CP_COMMIT();
    }

    for (int it = 0; it < KT; ++it) {
        cp_wait<1>();
        __syncthreads();
        if (it + 2 < KT) {
            int s = (it + 2) % 3;
            load_tile64(sb + s * STG, A, K, m0, (it + 2) * BK, tid);
            load_tile64(sb + s * STG + HSTG, B, K, n0, (it + 2) * BK, tid);
        }
        CP_COMMIT();

        const uint32_t as = sb + (it % 3) * STG;
        const uint32_t bs = as + HSTG;
        #pragma unroll
        for (int kk = 0; kk < 4; ++kk) {
            uint32_t a[2][4], b[8][2];
            #pragma unroll
            for (int mt = 0; mt < 2; ++mt)
                ldsm_x4(a[mt][0], a[mt][1], a[mt][2], a[mt][3], as + a_off[mt] + kk * 32);
            #pragma unroll
            for (int np = 0; np < 4; ++np)
                ldsm_x4(b[np*2][0], b[np*2][1], b[np*2+1][0], b[np*2+1][1],
                        bs + b_off[np] + kk * 32);
            #pragma unroll
            for (int mt = 0; mt < 2; ++mt)
                #pragma unroll
                for (int nt = 0; nt < 8; ++nt)
                    mma16816(acc[mt][nt], a[mt], b[nt]);
        }
    }

    const int r_lane = lane >> 2, c_lane = (lane & 3) * 2;
    __syncthreads();
    float* st = (float*)smem;
    #pragma unroll
    for (int mt = 0; mt < 2; ++mt) {
        int rl = wrow + mt * 16 + r_lane;
        #pragma unroll
        for (int nt = 0; nt < 8; ++nt) {
            int cl = wcol + nt * 8 + c_lane;
            float b0 = bias[n0 + cl], b1 = bias[n0 + cl + 1];
            st[rl * 129 + cl]           = acc[mt][nt][0] + b0;
            st[rl * 129 + cl + 1]       = acc[mt][nt][1] + b1;
            st[(rl + 8) * 129 + cl]     = acc[mt][nt][2] + b0;
            st[(rl + 8) * 129 + cl + 1] = acc[mt][nt][3] + b1;
        }
    }
    __syncthreads();
    #pragma unroll
    for (int i = 0; i < 64; ++i) {
        int idx = i * 256 + tid;
        int ci = idx >> 7, pi = idx & 127;
        size_t gi = (size_t)(n0 + ci) * PN + (m0 + pi);
        Cout[gi] = xres[gi] + st[pi * 129 + ci];
    }
}

// ---------------- launch ---------------------------------------------------------
extern "C" void kernel_launch(void* const* d_in, const int* in_sizes, int n_in,
                              void* d_out, int out_size)
{
    const float* x     = (const float*)d_in[0];
    const float* gamma = (const float*)d_in[1];
    const float* beta  = (const float*)d_in[2];
    const float* wq    = (const float*)d_in[3];
    const float* bq    = (const float*)d_in[4];
    const float* wk    = (const float*)d_in[5];
    const float* bk    = (const float*)d_in[6];
    const float* wv    = (const float*)d_in[7];
    const float* bv    = (const float*)d_in[8];
    const float* wp    = (const float*)d_in[9];
    const float* bp    = (const float*)d_in[10];
    float* out = (float*)d_out;

    __nv_bfloat16 *hl, *v, *o, *wt;
    uint8_t *q8, *k8, *vt8, *P8;
    float *rsum;
    cudaGetSymbolAddress((void**)&hl, g_hl);
    cudaGetSymbolAddress((void**)&q8, g_q8);
    cudaGetSymbolAddress((void**)&k8, g_k8);
    cudaGetSymbolAddress((void**)&v,  g_v);
    cudaGetSymbolAddress((void**)&vt8, g_vt8);
    cudaGetSymbolAddress((void**)&o,  g_o);
    cudaGetSymbolAddress((void**)&P8, g_P8);
    cudaGetSymbolAddress((void**)&rsum, g_rsum);
    cudaGetSymbolAddress((void**)&wt, g_wt);

    cudaFuncSetAttribute(gemm_qkv,      cudaFuncAttributeMaxDynamicSharedMemorySize, SMEM_PIPE);
    cudaFuncSetAttribute(gemm_fp8<1>,   cudaFuncAttributeMaxDynamicSharedMemorySize, SMEM_PIPE8);
    cudaFuncSetAttribute(gemm_fp8<0>,   cudaFuncAttributeMaxDynamicSharedMemorySize, SMEM_PIPE8);
    cudaFuncSetAttribute(gemm_transadd, cudaFuncAttributeMaxDynamicSharedMemorySize, SMEM_PIPE);

    dim3 tb(32, 32);
    const float scale = 0.044194173824159216f;  // 512^-0.5
    const size_t sQK = (size_t)HWN * CCH;
    const size_t sPP = (size_t)HWN * HWN;
    const size_t sVT = (size_t)CCH * HWN;

    gn_stats<<<GROUPS, 512>>>(x);
    norm_transpose<<<dim3(PN / 32, CCH / 32), tb>>>(x, gamma, beta, hl);

    W4 ws = { { wq, wk, wv, wp } };
    wtrans4<<<dim3(16, 16, 4), tb>>>(ws, wt);

    // fused q/k/v projections: q,k -> fp8; v -> bf16
    Ptr3 qkv = { bq, bk, bv, q8, k8, v };
    gemm_qkv<<<dim3(CCH / BN, PN / BM, 3), 256, SMEM_PIPE>>>(hl, wt, CCH, CCH, qkv);

    vtrans8<<<dim3(HWN / 32, CCH / 32, TT), tb>>>(v, vt8);

    // QK with fused exp: P8 = fp8(16 * exp(scale * q.k)); no separate softmax pass
    gemm_fp8<1><<<dim3(HWN / BN, HWN / BM, TT), 256, SMEM_PIPE8>>>(
        q8, k8, P8, nullptr, HWN, CCH, scale, sQK, sQK, sPP);

    // per-row sums of P8 (denominator; the x16 cancels)
    rowsum8<<<TT * HWN, 256>>>(P8, rsum);

    // PV with fused normalization: o = (P8 @ vt8^T) / rsum[row]
    gemm_fp8<0><<<dim3(CCH / BN, HWN / BM, TT), 256, SMEM_PIPE8>>>(
        P8, vt8, o, rsum, CCH, HWN, 1.f, sPP, sVT, sQK);

    // output projection with fused transpose + residual
    gemm_transadd<<<dim3(CCH / BN, PN / BM, 1), 256, SMEM_PIPE>>>(
        o, wt + 3 * CCH * CCH, bp, out, CCH, x);
}

// round 15
// speedup vs baseline: 1.5555x; 1.5555x over previous
#include <cuda_runtime.h>
#include <cuda_bf16.h>
#include <math.h>
#include <stdint.h>

#define CCH   512
#define TT    8
#define HWN   4096
#define PN    (TT*HWN)
#define GROUPS 32
#define GSIZE (16*PN)

// ---------------- scratch (device globals) ----------------------------------
__device__ float g_mean[GROUPS];
__device__ float g_rstd[GROUPS];
__device__ __nv_bfloat16 g_hl[(size_t)PN * CCH];
__device__ uint8_t       g_q8[(size_t)PN * CCH];
__device__ uint8_t       g_k8[(size_t)PN * CCH];
__device__ __nv_bfloat16 g_v [(size_t)PN * CCH];
__device__ uint8_t       g_vt8[(size_t)PN * CCH];
__device__ __nv_bfloat16 g_o [(size_t)PN * CCH];
__device__ __nv_bfloat16 g_P [(size_t)TT * HWN * HWN];   // 256 MB scores (bf16)
__device__ uint8_t       g_P8[(size_t)TT * HWN * HWN];   // 128 MB probs (e4m3 x256)
__device__ __nv_bfloat16 g_wt[4 * CCH * CCH];

struct Ptr3 {
    const float* b0; const float* b1; const float* b2;
    void* o0; void* o1; void* o2;
};
struct W4 { const float* w[4]; };

// ---------------- PTX helpers -------------------------------------------------
__device__ __forceinline__ uint32_t smem_u32(const void* p) {
    uint32_t a;
    asm("{ .reg .u64 t; cvta.to.shared.u64 t, %1; cvt.u32.u64 %0, t; }" : "=r"(a) : "l"(p));
    return a;
}
__device__ __forceinline__ void ldsm_x4(uint32_t& r0, uint32_t& r1, uint32_t& r2,
                                        uint32_t& r3, uint32_t addr) {
    asm volatile("ldmatrix.sync.aligned.m8n8.x4.shared.b16 {%0,%1,%2,%3}, [%4];"
                 : "=r"(r0), "=r"(r1), "=r"(r2), "=r"(r3) : "r"(addr));
}
__device__ __forceinline__ void mma16816(float* d, const uint32_t* a, const uint32_t* b) {
    asm volatile("mma.sync.aligned.m16n8k16.row.col.f32.bf16.bf16.f32 "
                 "{%0,%1,%2,%3}, {%4,%5,%6,%7}, {%8,%9}, {%0,%1,%2,%3};"
                 : "+f"(d[0]), "+f"(d[1]), "+f"(d[2]), "+f"(d[3])
                 : "r"(a[0]), "r"(a[1]), "r"(a[2]), "r"(a[3]), "r"(b[0]), "r"(b[1]));
}
__device__ __forceinline__ void mma16832(float* d, const uint32_t* a, const uint32_t* b) {
    asm volatile("mma.sync.aligned.m16n8k32.row.col.f32.e4m3.e4m3.f32 "
                 "{%0,%1,%2,%3}, {%4,%5,%6,%7}, {%8,%9}, {%0,%1,%2,%3};"
                 : "+f"(d[0]), "+f"(d[1]), "+f"(d[2]), "+f"(d[3])
                 : "r"(a[0]), "r"(a[1]), "r"(a[2]), "r"(a[3]), "r"(b[0]), "r"(b[1]));
}
__device__ __forceinline__ void cp16(uint32_t sm, const void* gp) {
    asm volatile("cp.async.cg.shared.global [%0], [%1], 16;" :: "r"(sm), "l"(gp) : "memory");
}
#define CP_COMMIT() asm volatile("cp.async.commit_group;" ::: "memory")
template<int W> __device__ __forceinline__ void cp_wait() {
    asm volatile("cp.async.wait_group %0;" :: "n"(W) : "memory");
}
// packed fp8 convert: lower byte = lo, upper = hi
__device__ __forceinline__ uint16_t fp8x2(float lo, float hi) {
    uint16_t r;
    asm("cvt.rn.satfinite.e4m3x2.f32 %0, %1, %2;" : "=h"(r) : "f"(hi), "f"(lo));
    return r;
}

// FMA-only exp
__device__ __forceinline__ float fexp(float x) {
    float y = fmaxf(x * 1.44269504f, -120.f);
    float n = rintf(y);
    float f = y - n;
    float p = 0.00133336f;
    p = fmaf(p, f, 0.00961813f);
    p = fmaf(p, f, 0.05550411f);
    p = fmaf(p, f, 0.24022651f);
    p = fmaf(p, f, 0.69314718f);
    p = fmaf(p, f, 1.0f);
    return __int_as_float(__float_as_int(p) + (((int)n) << 23));
}

// ---------------- group-norm stats --------------------------------------------
__global__ void __launch_bounds__(512) gn_stats(const float* __restrict__ x) {
    int g = blockIdx.x;
    const float4* p = (const float4*)(x + (size_t)g * GSIZE);
    float s = 0.f, ss = 0.f;
    for (int i = threadIdx.x; i < GSIZE / 4; i += 512) {
        float4 v = p[i];
        s  += v.x + v.y + v.z + v.w;
        ss += v.x * v.x + v.y * v.y + v.z * v.z + v.w * v.w;
    }
    __shared__ float shs[512], shq[512];
    shs[threadIdx.x] = s; shq[threadIdx.x] = ss;
    __syncthreads();
    for (int st = 256; st > 0; st >>= 1) {
        if (threadIdx.x < st) {
            shs[threadIdx.x] += shs[threadIdx.x + st];
            shq[threadIdx.x] += shq[threadIdx.x + st];
        }
        __syncthreads();
    }
    if (threadIdx.x == 0) {
        float m = shs[0] / (float)GSIZE;
        float var = shq[0] / (float)GSIZE - m * m;
        g_mean[g] = m;
        g_rstd[g] = rsqrtf(var + 1e-6f);
    }
}

// ---------------- normalize + transpose to channels-last (bf16) ---------------
__global__ void __launch_bounds__(1024) norm_transpose(
    const float* __restrict__ x, const float* __restrict__ gamma,
    const float* __restrict__ beta, __nv_bfloat16* __restrict__ hl)
{
    __shared__ float tile[32][33];
    int p0 = blockIdx.x * 32, c0 = blockIdx.y * 32;
    int c = c0 + threadIdx.y;
    tile[threadIdx.y][threadIdx.x] = x[(size_t)c * PN + p0 + threadIdx.x];
    __syncthreads();
    int cc = c0 + threadIdx.x;
    int g = cc >> 4;
    float a = gamma[cc] * g_rstd[g];
    float b = beta[cc] - g_mean[g] * a;
    hl[(size_t)(p0 + threadIdx.y) * CCH + cc] =
        __float2bfloat16(tile[threadIdx.x][threadIdx.y] * a + b);
}

// ---------------- batched weight transpose fp32 [K][N] -> bf16 [N][K] ----------
__global__ void __launch_bounds__(1024) wtrans4(W4 ws, __nv_bfloat16* __restrict__ Wt)
{
    __shared__ float t[32][33];
    const float* W = ws.w[blockIdx.z];
    __nv_bfloat16* Wo = Wt + (size_t)blockIdx.z * CCH * CCH;
    int k0 = blockIdx.y * 32, n0 = blockIdx.x * 32;
    t[threadIdx.y][threadIdx.x] = W[(size_t)(k0 + threadIdx.y) * CCH + n0 + threadIdx.x];
    __syncthreads();
    Wo[(size_t)(n0 + threadIdx.y) * CCH + k0 + threadIdx.x] =
        __float2bfloat16(t[threadIdx.x][threadIdx.y]);
}

// ---------------- V transpose bf16 [t*4096+p][c] -> fp8 [t][c][p] ---------------
__global__ void __launch_bounds__(1024) vtrans8(const __nv_bfloat16* __restrict__ v,
                                                uint8_t* __restrict__ vt8)
{
    __shared__ __nv_bfloat16 t[32][33];
    int ts = blockIdx.z, p0 = blockIdx.x * 32, c0 = blockIdx.y * 32;
    t[threadIdx.y][threadIdx.x] =
        v[(size_t)(ts * HWN + p0 + threadIdx.y) * CCH + c0 + threadIdx.x];
    __syncthreads();
    float val = __bfloat162float(t[threadIdx.x][threadIdx.y]);
    uint16_t pk = fp8x2(val, 0.f);
    vt8[(size_t)ts * CCH * HWN + (size_t)(c0 + threadIdx.y) * HWN + p0 + threadIdx.x] =
        (uint8_t)(pk & 0xFF);
}

// =================== bf16 GEMM 128x128xBK64 (R6 geometry, 2 CTAs/SM) ============
#define BK   64
#define ROWB 144
#define BM 128
#define BN 128
#define HSTG (BM * ROWB)          // 18432
#define STG  (2 * HSTG)           // 36864
#define SMEM_PIPE (3 * STG)       // 110592

__device__ __forceinline__ void load_tile64(uint32_t sm_base, const __nv_bfloat16* g,
                                            int ld, int row0, int k0, int tid)
{
    #pragma unroll
    for (int i = 0; i < 4; ++i) {
        int id  = i * 256 + tid;
        int row = id >> 3;
        int ch  = id & 7;
        cp16(sm_base + row * ROWB + ch * 16, g + (size_t)(row0 + row) * ld + k0 + ch * 8);
    }
}

__global__ void __launch_bounds__(256, 2) gemm_qkv(
    const __nv_bfloat16* __restrict__ A, const __nv_bfloat16* __restrict__ B,
    int N, int K, Ptr3 p3)
{
    extern __shared__ __nv_bfloat16 smem[];
    const uint32_t sb = smem_u32(smem);
    const int tid = threadIdx.x, wid = tid >> 5, lane = tid & 31;
    const int m0 = blockIdx.y * BM, n0 = blockIdx.x * BN;
    const int z = blockIdx.z;

    B += (size_t)z * (CCH * CCH);
    const float* bias_p = (z == 0) ? p3.b0 : (z == 1) ? p3.b1 : p3.b2;
    void* outp          = (z == 0) ? p3.o0 : (z == 1) ? p3.o1 : p3.o2;

    const int wm = wid & 3, wn = wid >> 2;
    const int wrow = wm * 32, wcol = wn * 64;
    const int KT = K / BK;

    uint32_t a_off[2];
    #pragma unroll
    for (int mt = 0; mt < 2; ++mt)
        a_off[mt] = (wrow + mt * 16 + (lane & 15)) * ROWB + ((lane >> 4) << 4);
    uint32_t b_off[4];
    #pragma unroll
    for (int np = 0; np < 4; ++np) {
        int n  = wcol + np * 16 + (lane & 7) + ((lane >> 4) << 3);
        int kf = ((lane >> 3) & 1) << 3;
        b_off[np] = n * ROWB + kf * 2;
    }

    float acc[2][8][4];
    #pragma unroll
    for (int i = 0; i < 2; ++i)
        #pragma unroll
        for (int j = 0; j < 8; ++j)
            #pragma unroll
            for (int q = 0; q < 4; ++q) acc[i][j][q] = 0.f;

    #pragma unroll
    for (int s = 0; s < 2; ++s) {
        load_tile64(sb + s * STG, A, K, m0, s * BK, tid);
        load_tile64(sb + s * STG + HSTG, B, K, n0, s * BK, tid);
        CP_COMMIT();
    }

    for (int it = 0; it < KT; ++it) {
        cp_wait<1>();
        __syncthreads();
        if (it + 2 < KT) {
            int s = (it + 2) % 3;
            load_tile64(sb + s * STG, A, K, m0, (it + 2) * BK, tid);
            load_tile64(sb + s * STG + HSTG, B, K, n0, (it + 2) * BK, tid);
        }
        CP_COMMIT();

        const uint32_t as = sb + (it % 3) * STG;
        const uint32_t bs = as + HSTG;
        #pragma unroll
        for (int kk = 0; kk < 4; ++kk) {
            uint32_t a[2][4], b[8][2];
            #pragma unroll
            for (int mt = 0; mt < 2; ++mt)
                ldsm_x4(a[mt][0], a[mt][1], a[mt][2], a[mt][3], as + a_off[mt] + kk * 32);
            #pragma unroll
            for (int np = 0; np < 4; ++np)
                ldsm_x4(b[np*2][0], b[np*2][1], b[np*2+1][0], b[np*2+1][1],
                        bs + b_off[np] + kk * 32);
            #pragma unroll
            for (int mt = 0; mt < 2; ++mt)
                #pragma unroll
                for (int nt = 0; nt < 8; ++nt)
                    mma16816(acc[mt][nt], a[mt], b[nt]);
        }
    }

    const int r_lane = lane >> 2, c_lane = (lane & 3) * 2;
    const bool f8out = (z != 2);
    #pragma unroll
    for (int mt = 0; mt < 2; ++mt) {
        int r0 = m0 + wrow + mt * 16 + r_lane;
        #pragma unroll
        for (int nt = 0; nt < 8; ++nt) {
            int c = n0 + wcol + nt * 8 + c_lane;
            float b0 = bias_p[c], b1 = bias_p[c + 1];
            float v0 = acc[mt][nt][0] + b0, v1 = acc[mt][nt][1] + b1;
            float v2 = acc[mt][nt][2] + b0, v3 = acc[mt][nt][3] + b1;
            if (f8out) {
                uint8_t* Cb = (uint8_t*)outp;
                *(uint16_t*)(Cb + (size_t)r0 * N + c)       = fp8x2(v0, v1);
                *(uint16_t*)(Cb + (size_t)(r0 + 8) * N + c) = fp8x2(v2, v3);
            } else {
                __nv_bfloat16* Cb = (__nv_bfloat16*)outp;
                *(__nv_bfloat162*)(Cb + (size_t)r0 * N + c)       = __floats2bfloat162_rn(v0, v1);
                *(__nv_bfloat162*)(Cb + (size_t)(r0 + 8) * N + c) = __floats2bfloat162_rn(v2, v3);
            }
        }
    }
}

// =================== FP8 GEMM 128x128xBK64 e4m3, 3 stages, 2 CTAs/SM ============
#define ROWB8 80
#define HSTG8 (BM * ROWB8)        // 10240
#define STG8  (2 * HSTG8)         // 20480
#define SMEM_PIPE8 (3 * STG8)     // 61440

__device__ __forceinline__ void load_tile8(uint32_t sm_base, const uint8_t* g,
                                           int ld, int row0, int k0, int tid)
{
    #pragma unroll
    for (int i = 0; i < 2; ++i) {
        int id  = i * 256 + tid;
        int row = id >> 2;
        int ch  = id & 3;
        cp16(sm_base + row * ROWB8 + ch * 16, g + (size_t)(row0 + row) * ld + k0 + ch * 16);
    }
}

__global__ void __launch_bounds__(256, 2) gemm_fp8(
    const uint8_t* __restrict__ A, const uint8_t* __restrict__ B,
    __nv_bfloat16* __restrict__ C,
    int N, int K, float scale, size_t sA, size_t sB, size_t sC)
{
    extern __shared__ __nv_bfloat16 smem[];
    const uint32_t sb = smem_u32(smem);
    const int tid = threadIdx.x, wid = tid >> 5, lane = tid & 31;
    const int m0 = blockIdx.y * BM, n0 = blockIdx.x * BN;
    const int z = blockIdx.z;
    A += (size_t)z * sA;
    B += (size_t)z * sB;
    C += (size_t)z * sC;

    const int wm = wid & 3, wn = wid >> 2;
    const int wrow = wm * 32, wcol = wn * 64;
    const int KT = K / BK;

    uint32_t a_off[2];
    #pragma unroll
    for (int mt = 0; mt < 2; ++mt)
        a_off[mt] = (wrow + mt * 16 + (lane & 15)) * ROWB8 + ((lane >> 4) << 4);
    uint32_t b_off[4];
    #pragma unroll
    for (int np = 0; np < 4; ++np) {
        int n = wcol + np * 16 + (lane & 7) + ((lane >> 4) << 3);
        b_off[np] = n * ROWB8 + (((lane >> 3) & 1) << 4);
    }

    float acc[2][8][4];
    #pragma unroll
    for (int i = 0; i < 2; ++i)
        #pragma unroll
        for (int j = 0; j < 8; ++j)
            #pragma unroll
            for (int q = 0; q < 4; ++q) acc[i][j][q] = 0.f;

    #pragma unroll
    for (int s = 0; s < 2; ++s) {
        load_tile8(sb + s * STG8, A, K, m0, s * BK, tid);
        load_tile8(sb + s * STG8 + HSTG8, B, K, n0, s * BK, tid);
        CP_COMMIT();
    }

    for (int it = 0; it < KT; ++it) {
        cp_wait<1>();
        __syncthreads();
        if (it + 2 < KT) {
            int s = (it + 2) % 3;
            load_tile8(sb + s * STG8, A, K, m0, (it + 2) * BK, tid);
            load_tile8(sb + s * STG8 + HSTG8, B, K, n0, (it + 2) * BK, tid);
        }
        CP_COMMIT();

        const uint32_t as = sb + (it % 3) * STG8;
        const uint32_t bs = as + HSTG8;
        #pragma unroll
        for (int kk = 0; kk < 2; ++kk) {     // 2 x k32 per BK64
            uint32_t a[2][4], b[8][2];
            #pragma unroll
            for (int mt = 0; mt < 2; ++mt)
                ldsm_x4(a[mt][0], a[mt][1], a[mt][2], a[mt][3], as + a_off[mt] + kk * 32);
            #pragma unroll
            for (int np = 0; np < 4; ++np)
                ldsm_x4(b[np*2][0], b[np*2][1], b[np*2+1][0], b[np*2+1][1],
                        bs + b_off[np] + kk * 32);
            #pragma unroll
            for (int mt = 0; mt < 2; ++mt)
                #pragma unroll
                for (int nt = 0; nt < 8; ++nt)
                    mma16832(acc[mt][nt], a[mt], b[nt]);
        }
    }

    const int r_lane = lane >> 2, c_lane = (lane & 3) * 2;
    #pragma unroll
    for (int mt = 0; mt < 2; ++mt) {
        int r0 = m0 + wrow + mt * 16 + r_lane;
        #pragma unroll
        for (int nt = 0; nt < 8; ++nt) {
            int c = n0 + wcol + nt * 8 + c_lane;
            *(__nv_bfloat162*)(C + (size_t)r0 * N + c) =
                __floats2bfloat162_rn(acc[mt][nt][0] * scale, acc[mt][nt][1] * scale);
            *(__nv_bfloat162*)(C + (size_t)(r0 + 8) * N + c) =
                __floats2bfloat162_rn(acc[mt][nt][2] * scale, acc[mt][nt][3] * scale);
        }
    }
}

// =================== 128x128xBK64 bf16 GEMM with fused transpose+residual =======
__global__ void __launch_bounds__(256, 2) gemm_transadd(
    const __nv_bfloat16* __restrict__ A, const __nv_bfloat16* __restrict__ B,
    const float* __restrict__ bias, float* __restrict__ Cout,
    int K, const float* __restrict__ xres)
{
    extern __shared__ __nv_bfloat16 smem[];
    const uint32_t sb = smem_u32(smem);
    const int tid = threadIdx.x, wid = tid >> 5, lane = tid & 31;
    const int m0 = blockIdx.y * BM, n0 = blockIdx.x * BN;

    const int wm = wid & 3, wn = wid >> 2;
    const int wrow = wm * 32, wcol = wn * 64;
    const int KT = K / BK;

    uint32_t a_off[2];
    #pragma unroll
    for (int mt = 0; mt < 2; ++mt)
        a_off[mt] = (wrow + mt * 16 + (lane & 15)) * ROWB + ((lane >> 4) << 4);
    uint32_t b_off[4];
    #pragma unroll
    for (int np = 0; np < 4; ++np) {
        int n  = wcol + np * 16 + (lane & 7) + ((lane >> 4) << 3);
        int kf = ((lane >> 3) & 1) << 3;
        b_off[np] = n * ROWB + kf * 2;
    }

    float acc[2][8][4];
    #pragma unroll
    for (int i = 0; i < 2; ++i)
        #pragma unroll
        for (int j = 0; j < 8; ++j)
            #pragma unroll
            for (int q = 0; q < 4; ++q) acc[i][j][q] = 0.f;

    #pragma unroll
    for (int s = 0; s < 2; ++s) {
        load_tile64(sb + s * STG, A, K, m0, s * BK, tid);
        load_tile64(sb + s * STG + HSTG, B, K, n0, s * BK, tid);
        CP_COMMIT();
    }

    for (int it = 0; it < KT; ++it) {
        cp_wait<1>();
        __syncthreads();
        if (it + 2 < KT) {
            int s = (it + 2) % 3;
            load_tile64(sb + s * STG, A, K, m0, (it + 2) * BK, tid);
            load_tile64(sb + s * STG + HSTG, B, K, n0, (it + 2) * BK, tid);
        }
        CP_COMMIT();

        const uint32_t as = sb + (it % 3) * STG;
        const uint32_t bs = as + HSTG;
        #pragma unroll
        for (int kk = 0; kk < 4; ++kk) {
            uint32_t a[2][4], b[8][2];
            #pragma unroll
            for (int mt = 0; mt < 2; ++mt)
                ldsm_x4(a[mt][0], a[mt][1], a[mt][2], a[mt][3], as + a_off[mt] + kk * 32);
            #pragma unroll
            for (int np = 0; np < 4; ++np)
                ldsm_x4(b[np*2][0], b[np*2][1], b[np*2+1][0], b[np*2+1][1],
                        bs + b_off[np] + kk * 32);
            #pragma unroll
            for (int mt = 0; mt < 2; ++mt)
                #pragma unroll
                for (int nt = 0; nt < 8; ++nt)
                    mma16816(acc[mt][nt], a[mt], b[nt]);
        }
    }

    const int r_lane = lane >> 2, c_lane = (lane & 3) * 2;
    __syncthreads();
    float* st = (float*)smem;
    #pragma unroll
    for (int mt = 0; mt < 2; ++mt) {
        int rl = wrow + mt * 16 + r_lane;
        #pragma unroll
        for (int nt = 0; nt < 8; ++nt) {
            int cl = wcol + nt * 8 + c_lane;
            float b0 = bias[n0 + cl], b1 = bias[n0 + cl + 1];
            st[rl * 129 + cl]           = acc[mt][nt][0] + b0;
            st[rl * 129 + cl + 1]       = acc[mt][nt][1] + b1;
            st[(rl + 8) * 129 + cl]     = acc[mt][nt][2] + b0;
            st[(rl + 8) * 129 + cl + 1] = acc[mt][nt][3] + b1;
        }
    }
    __syncthreads();
    #pragma unroll
    for (int i = 0; i < 64; ++i) {
        int idx = i * 256 + tid;
        int ci = idx >> 7, pi = idx & 127;
        size_t gi = (size_t)(n0 + ci) * PN + (m0 + pi);
        Cout[gi] = xres[gi] + st[pi * 129 + ci];
    }
}

// ---------------- softmax: bf16 scores -> fp8 probs (x256) ----------------------
__global__ void __launch_bounds__(256) softmax8(const __nv_bfloat16* __restrict__ P,
                                                uint8_t* __restrict__ P8)
{
    __shared__ float redm[8], reds[8];
    const uint4* row = (const uint4*)(P + (size_t)blockIdx.x * HWN);
    uint4 d[2];
    float f[16];
    d[0] = row[threadIdx.x];
    d[1] = row[threadIdx.x + 256];
    #pragma unroll
    for (int j = 0; j < 2; ++j) {
        const __nv_bfloat162* h = (const __nv_bfloat162*)&d[j];
        #pragma unroll
        for (int q = 0; q < 4; ++q) {
            float2 t = __bfloat1622float2(h[q]);
            f[j * 8 + q * 2] = t.x; f[j * 8 + q * 2 + 1] = t.y;
        }
    }

    float m = -3.4e38f;
    #pragma unroll
    for (int i = 0; i < 16; ++i) m = fmaxf(m, f[i]);
    #pragma unroll
    for (int o = 16; o > 0; o >>= 1) m = fmaxf(m, __shfl_xor_sync(0xffffffffu, m, o));
    int wid = threadIdx.x >> 5, lane = threadIdx.x & 31;
    if (lane == 0) redm[wid] = m;
    __syncthreads();
    if (wid == 0) {
        float t = (lane < 8) ? redm[lane] : -3.4e38f;
        #pragma unroll
        for (int o = 16; o > 0; o >>= 1) t = fmaxf(t, __shfl_xor_sync(0xffffffffu, t, o));
        if (lane == 0) redm[0] = t;
    }
    __syncthreads();
    m = redm[0];

    float s = 0.f;
    #pragma unroll
    for (int i = 0; i < 16; ++i) { f[i] = fexp(f[i] - m); s += f[i]; }
    #pragma unroll
    for (int o = 16; o > 0; o >>= 1) s += __shfl_xor_sync(0xffffffffu, s, o);
    if (lane == 0) reds[wid] = s;
    __syncthreads();
    if (wid == 0) {
        float t = (lane < 8) ? reds[lane] : 0.f;
        #pragma unroll
        for (int o = 16; o > 0; o >>= 1) t += __shfl_xor_sync(0xffffffffu, t, o);
        if (lane == 0) reds[0] = t;
    }
    __syncthreads();
    float inv = 256.f / reds[0];     // x256 so probs live in e4m3 normal range

    uint8_t* p8row = P8 + (size_t)blockIdx.x * HWN;
    #pragma unroll
    for (int j = 0; j < 2; ++j) {
        uint16_t w[4];
        #pragma unroll
        for (int q = 0; q < 4; ++q)
            w[q] = fp8x2(f[j * 8 + q * 2] * inv, f[j * 8 + q * 2 + 1] * inv);
        uint2 outv;
        outv.x = (uint32_t)w[0] | ((uint32_t)w[1] << 16);
        outv.y = (uint32_t)w[2] | ((uint32_t)w[3] << 16);
        *(uint2*)(p8row + (threadIdx.x + j * 256) * 8) = outv;
    }
}

// ---------------- launch ---------------------------------------------------------
extern "C" void kernel_launch(void* const* d_in, const int* in_sizes, int n_in,
                              void* d_out, int out_size)
{
    const float* x     = (const float*)d_in[0];
    const float* gamma = (const float*)d_in[1];
    const float* beta  = (const float*)d_in[2];
    const float* wq    = (const float*)d_in[3];
    const float* bq    = (const float*)d_in[4];
    const float* wk    = (const float*)d_in[5];
    const float* bk    = (const float*)d_in[6];
    const float* wv    = (const float*)d_in[7];
    const float* bv    = (const float*)d_in[8];
    const float* wp    = (const float*)d_in[9];
    const float* bp    = (const float*)d_in[10];
    float* out = (float*)d_out;

    __nv_bfloat16 *hl, *v, *o, *P, *wt;
    uint8_t *q8, *k8, *vt8, *P8;
    cudaGetSymbolAddress((void**)&hl, g_hl);
    cudaGetSymbolAddress((void**)&q8, g_q8);
    cudaGetSymbolAddress((void**)&k8, g_k8);
    cudaGetSymbolAddress((void**)&v,  g_v);
    cudaGetSymbolAddress((void**)&vt8, g_vt8);
    cudaGetSymbolAddress((void**)&o,  g_o);
    cudaGetSymbolAddress((void**)&P,  g_P);
    cudaGetSymbolAddress((void**)&P8, g_P8);
    cudaGetSymbolAddress((void**)&wt, g_wt);

    cudaFuncSetAttribute(gemm_qkv,      cudaFuncAttributeMaxDynamicSharedMemorySize, SMEM_PIPE);
    cudaFuncSetAttribute(gemm_fp8,      cudaFuncAttributeMaxDynamicSharedMemorySize, SMEM_PIPE8);
    cudaFuncSetAttribute(gemm_transadd, cudaFuncAttributeMaxDynamicSharedMemorySize, SMEM_PIPE);

    dim3 tb(32, 32);

    gn_stats<<<GROUPS, 512>>>(x);
    norm_transpose<<<dim3(PN / 32, CCH / 32), tb>>>(x, gamma, beta, hl);

    W4 ws = { { wq, wk, wv, wp } };
    wtrans4<<<dim3(16, 16, 4), tb>>>(ws, wt);

    // fused q/k/v projections: q,k -> fp8; v -> bf16
    Ptr3 qkv = { bq, bk, bv, q8, k8, v };
    gemm_qkv<<<dim3(CCH / BN, PN / BM, 3), 256, SMEM_PIPE>>>(hl, wt, CCH, CCH, qkv);

    vtrans8<<<dim3(HWN / 32, CCH / 32, TT), tb>>>(v, vt8);

    const float scale = 0.044194173824159216f;  // 512^-0.5

    // scores: fp8 GEMM, bf16 out (scale fused), batched over 8 t-slices
    gemm_fp8<<<dim3(HWN / BN, HWN / BM, TT), 256, SMEM_PIPE8>>>(
        q8, k8, P, HWN, CCH, scale,
        (size_t)HWN * CCH, (size_t)HWN * CCH, (size_t)HWN * HWN);

    softmax8<<<TT * HWN, 256>>>(P, P8);

    // PV: fp8 GEMM, o = (P8 @ vt8^T) / 256
    gemm_fp8<<<dim3(CCH / BN, HWN / BM, TT), 256, SMEM_PIPE8>>>(
        P8, vt8, o, CCH, HWN, 1.f / 256.f,
        (size_t)HWN * HWN, (size_t)CCH * HWN, (size_t)HWN * CCH);

    // output projection with fused transpose + residual (bf16)
    gemm_transadd<<<dim3(CCH / BN, PN / BM, 1), 256, SMEM_PIPE>>>(
        o, wt + 3 * CCH * CCH, bp, out, CCH, x);
}

// round 16
// speedup vs baseline: 1.5920x; 1.0235x over previous
#include <cuda_runtime.h>
#include <cuda_bf16.h>
#include <math.h>
#include <stdint.h>

#define CCH   512
#define TT    8
#define HWN   4096
#define PN    (TT*HWN)
#define GROUPS 32
#define GSIZE (16*PN)

// ---------------- scratch (device globals) ----------------------------------
__device__ float g_mean[GROUPS];
__device__ float g_rstd[GROUPS];
__device__ __nv_bfloat16 g_hl[(size_t)PN * CCH];
__device__ uint8_t       g_q8[(size_t)PN * CCH];
__device__ uint8_t       g_k8[(size_t)PN * CCH];
__device__ uint8_t       g_vt8[(size_t)PN * CCH];
__device__ __nv_bfloat16 g_o [(size_t)PN * CCH];
__device__ __nv_bfloat16 g_P [(size_t)TT * HWN * HWN];   // 256 MB scores (bf16)
__device__ uint8_t       g_P8[(size_t)TT * HWN * HWN];   // 128 MB probs (e4m3 x256)
__device__ __nv_bfloat16 g_wt[4 * CCH * CCH];

struct Ptr3 {
    const float* b0; const float* b1; const float* b2;
    void* o0; void* o1; void* o2;
};
struct W4 { const float* w[4]; };

// ---------------- PTX helpers -------------------------------------------------
__device__ __forceinline__ uint32_t smem_u32(const void* p) {
    uint32_t a;
    asm("{ .reg .u64 t; cvta.to.shared.u64 t, %1; cvt.u32.u64 %0, t; }" : "=r"(a) : "l"(p));
    return a;
}
__device__ __forceinline__ void ldsm_x4(uint32_t& r0, uint32_t& r1, uint32_t& r2,
                                        uint32_t& r3, uint32_t addr) {
    asm volatile("ldmatrix.sync.aligned.m8n8.x4.shared.b16 {%0,%1,%2,%3}, [%4];"
                 : "=r"(r0), "=r"(r1), "=r"(r2), "=r"(r3) : "r"(addr));
}
__device__ __forceinline__ void mma16816(float* d, const uint32_t* a, const uint32_t* b) {
    asm volatile("mma.sync.aligned.m16n8k16.row.col.f32.bf16.bf16.f32 "
                 "{%0,%1,%2,%3}, {%4,%5,%6,%7}, {%8,%9}, {%0,%1,%2,%3};"
                 : "+f"(d[0]), "+f"(d[1]), "+f"(d[2]), "+f"(d[3])
                 : "r"(a[0]), "r"(a[1]), "r"(a[2]), "r"(a[3]), "r"(b[0]), "r"(b[1]));
}
__device__ __forceinline__ void mma16832(float* d, const uint32_t* a, const uint32_t* b) {
    asm volatile("mma.sync.aligned.m16n8k32.row.col.f32.e4m3.e4m3.f32 "
                 "{%0,%1,%2,%3}, {%4,%5,%6,%7}, {%8,%9}, {%0,%1,%2,%3};"
                 : "+f"(d[0]), "+f"(d[1]), "+f"(d[2]), "+f"(d[3])
                 : "r"(a[0]), "r"(a[1]), "r"(a[2]), "r"(a[3]), "r"(b[0]), "r"(b[1]));
}
__device__ __forceinline__ void cp16(uint32_t sm, const void* gp) {
    asm volatile("cp.async.cg.shared.global [%0], [%1], 16;" :: "r"(sm), "l"(gp) : "memory");
}
#define CP_COMMIT() asm volatile("cp.async.commit_group;" ::: "memory")
template<int W> __device__ __forceinline__ void cp_wait() {
    asm volatile("cp.async.wait_group %0;" :: "n"(W) : "memory");
}
// packed fp8 convert: lower byte = lo, upper = hi
__device__ __forceinline__ uint16_t fp8x2(float lo, float hi) {
    uint16_t r;
    asm("cvt.rn.satfinite.e4m3x2.f32 %0, %1, %2;" : "=h"(r) : "f"(hi), "f"(lo));
    return r;
}

// FMA-only exp
__device__ __forceinline__ float fexp(float x) {
    float y = fmaxf(x * 1.44269504f, -120.f);
    float n = rintf(y);
    float f = y - n;
    float p = 0.00133336f;
    p = fmaf(p, f, 0.00961813f);
    p = fmaf(p, f, 0.05550411f);
    p = fmaf(p, f, 0.24022651f);
    p = fmaf(p, f, 0.69314718f);
    p = fmaf(p, f, 1.0f);
    return __int_as_float(__float_as_int(p) + (((int)n) << 23));
}

// ---------------- group-norm stats --------------------------------------------
__global__ void __launch_bounds__(512) gn_stats(const float* __restrict__ x) {
    int g = blockIdx.x;
    const float4* p = (const float4*)(x + (size_t)g * GSIZE);
    float s = 0.f, ss = 0.f;
    for (int i = threadIdx.x; i < GSIZE / 4; i += 512) {
        float4 v = p[i];
        s  += v.x + v.y + v.z + v.w;
        ss += v.x * v.x + v.y * v.y + v.z * v.z + v.w * v.w;
    }
    __shared__ float shs[512], shq[512];
    shs[threadIdx.x] = s; shq[threadIdx.x] = ss;
    __syncthreads();
    for (int st = 256; st > 0; st >>= 1) {
        if (threadIdx.x < st) {
            shs[threadIdx.x] += shs[threadIdx.x + st];
            shq[threadIdx.x] += shq[threadIdx.x + st];
        }
        __syncthreads();
    }
    if (threadIdx.x == 0) {
        float m = shs[0] / (float)GSIZE;
        float var = shq[0] / (float)GSIZE - m * m;
        g_mean[g] = m;
        g_rstd[g] = rsqrtf(var + 1e-6f);
    }
}

// ---------------- normalize + transpose to channels-last (bf16) ---------------
__global__ void __launch_bounds__(1024) norm_transpose(
    const float* __restrict__ x, const float* __restrict__ gamma,
    const float* __restrict__ beta, __nv_bfloat16* __restrict__ hl)
{
    __shared__ float tile[32][33];
    int p0 = blockIdx.x * 32, c0 = blockIdx.y * 32;
    int c = c0 + threadIdx.y;
    tile[threadIdx.y][threadIdx.x] = x[(size_t)c * PN + p0 + threadIdx.x];
    __syncthreads();
    int cc = c0 + threadIdx.x;
    int g = cc >> 4;
    float a = gamma[cc] * g_rstd[g];
    float b = beta[cc] - g_mean[g] * a;
    hl[(size_t)(p0 + threadIdx.y) * CCH + cc] =
        __float2bfloat16(tile[threadIdx.x][threadIdx.y] * a + b);
}

// ---------------- batched weight transpose fp32 [K][N] -> bf16 [N][K] ----------
__global__ void __launch_bounds__(1024) wtrans4(W4 ws, __nv_bfloat16* __restrict__ Wt)
{
    __shared__ float t[32][33];
    const float* W = ws.w[blockIdx.z];
    __nv_bfloat16* Wo = Wt + (size_t)blockIdx.z * CCH * CCH;
    int k0 = blockIdx.y * 32, n0 = blockIdx.x * 32;
    t[threadIdx.y][threadIdx.x] = W[(size_t)(k0 + threadIdx.y) * CCH + n0 + threadIdx.x];
    __syncthreads();
    Wo[(size_t)(n0 + threadIdx.y) * CCH + k0 + threadIdx.x] =
        __float2bfloat16(t[threadIdx.x][threadIdx.y]);
}

// =================== bf16 GEMM 128x128xBK64 (R6 geometry, 2 CTAs/SM) ============
// z in {0,1}: q,k -> fp8 row-major. z==2: v -> fp8 TRANSPOSED (vt8[t][c][p]) via
// smem staging in the (now free) pipeline buffers.
#define BK   64
#define ROWB 144
#define BM 128
#define BN 128
#define HSTG (BM * ROWB)          // 18432
#define STG  (2 * HSTG)           // 36864
#define SMEM_PIPE (3 * STG)       // 110592

__device__ __forceinline__ void load_tile64(uint32_t sm_base, const __nv_bfloat16* g,
                                            int ld, int row0, int k0, int tid)
{
    #pragma unroll
    for (int i = 0; i < 4; ++i) {
        int id  = i * 256 + tid;
        int row = id >> 3;
        int ch  = id & 7;
        cp16(sm_base + row * ROWB + ch * 16, g + (size_t)(row0 + row) * ld + k0 + ch * 8);
    }
}

__global__ void __launch_bounds__(256, 2) gemm_qkv(
    const __nv_bfloat16* __restrict__ A, const __nv_bfloat16* __restrict__ B,
    int N, int K, Ptr3 p3)
{
    extern __shared__ __nv_bfloat16 smem[];
    const uint32_t sb = smem_u32(smem);
    const int tid = threadIdx.x, wid = tid >> 5, lane = tid & 31;
    const int m0 = blockIdx.y * BM, n0 = blockIdx.x * BN;
    const int z = blockIdx.z;

    B += (size_t)z * (CCH * CCH);
    const float* bias_p = (z == 0) ? p3.b0 : (z == 1) ? p3.b1 : p3.b2;
    void* outp          = (z == 0) ? p3.o0 : (z == 1) ? p3.o1 : p3.o2;

    const int wm = wid & 3, wn = wid >> 2;
    const int wrow = wm * 32, wcol = wn * 64;
    const int KT = K / BK;

    uint32_t a_off[2];
    #pragma unroll
    for (int mt = 0; mt < 2; ++mt)
        a_off[mt] = (wrow + mt * 16 + (lane & 15)) * ROWB + ((lane >> 4) << 4);
    uint32_t b_off[4];
    #pragma unroll
    for (int np = 0; np < 4; ++np) {
        int n  = wcol + np * 16 + (lane & 7) + ((lane >> 4) << 3);
        int kf = ((lane >> 3) & 1) << 3;
        b_off[np] = n * ROWB + kf * 2;
    }

    float acc[2][8][4];
    #pragma unroll
    for (int i = 0; i < 2; ++i)
        #pragma unroll
        for (int j = 0; j < 8; ++j)
            #pragma unroll
            for (int q = 0; q < 4; ++q) acc[i][j][q] = 0.f;

    #pragma unroll
    for (int s = 0; s < 2; ++s) {
        load_tile64(sb + s * STG, A, K, m0, s * BK, tid);
        load_tile64(sb + s * STG + HSTG, B, K, n0, s * BK, tid);
        CP_COMMIT();
    }

    for (int it = 0; it < KT; ++it) {
        cp_wait<1>();
        __syncthreads();
        if (it + 2 < KT) {
            int s = (it + 2) % 3;
            load_tile64(sb + s * STG, A, K, m0, (it + 2) * BK, tid);
            load_tile64(sb + s * STG + HSTG, B, K, n0, (it + 2) * BK, tid);
        }
        CP_COMMIT();

        const uint32_t as = sb + (it % 3) * STG;
        const uint32_t bs = as + HSTG;
        #pragma unroll
        for (int kk = 0; kk < 4; ++kk) {
            uint32_t a[2][4], b[8][2];
            #pragma unroll
            for (int mt = 0; mt < 2; ++mt)
                ldsm_x4(a[mt][0], a[mt][1], a[mt][2], a[mt][3], as + a_off[mt] + kk * 32);
            #pragma unroll
            for (int np = 0; np < 4; ++np)
                ldsm_x4(b[np*2][0], b[np*2][1], b[np*2+1][0], b[np*2+1][1],
                        bs + b_off[np] + kk * 32);
            #pragma unroll
            for (int mt = 0; mt < 2; ++mt)
                #pragma unroll
                for (int nt = 0; nt < 8; ++nt)
                    mma16816(acc[mt][nt], a[mt], b[nt]);
        }
    }

    const int r_lane = lane >> 2, c_lane = (lane & 3) * 2;

    if (z != 2) {
        // q,k: fp8 row-major [p][c]
        uint8_t* Cb = (uint8_t*)outp;
        #pragma unroll
        for (int mt = 0; mt < 2; ++mt) {
            int r0 = m0 + wrow + mt * 16 + r_lane;
            #pragma unroll
            for (int nt = 0; nt < 8; ++nt) {
                int c = n0 + wcol + nt * 8 + c_lane;
                float b0 = bias_p[c], b1 = bias_p[c + 1];
                *(uint16_t*)(Cb + (size_t)r0 * N + c) =
                    fp8x2(acc[mt][nt][0] + b0, acc[mt][nt][1] + b1);
                *(uint16_t*)(Cb + (size_t)(r0 + 8) * N + c) =
                    fp8x2(acc[mt][nt][2] + b0, acc[mt][nt][3] + b1);
            }
        }
    } else {
        // v: transposed fp8 [t][c][p] via smem staging (pipeline smem is free now)
        cp_wait<0>();
        __syncthreads();
        uint8_t* vts = (uint8_t*)smem;      // [col][row], row-stride 144 (16-aligned)
        #pragma unroll
        for (int mt = 0; mt < 2; ++mt) {
            int rl = wrow + mt * 16 + r_lane;
            #pragma unroll
            for (int nt = 0; nt < 8; ++nt) {
                int cl = wcol + nt * 8 + c_lane;
                float b0 = bias_p[n0 + cl], b1 = bias_p[n0 + cl + 1];
                uint16_t wlo = fp8x2(acc[mt][nt][0] + b0, acc[mt][nt][1] + b1);
                uint16_t whi = fp8x2(acc[mt][nt][2] + b0, acc[mt][nt][3] + b1);
                vts[cl * 144 + rl]           = (uint8_t)(wlo & 0xFF);
                vts[(cl + 1) * 144 + rl]     = (uint8_t)(wlo >> 8);
                vts[cl * 144 + rl + 8]       = (uint8_t)(whi & 0xFF);
                vts[(cl + 1) * 144 + rl + 8] = (uint8_t)(whi >> 8);
            }
        }
        __syncthreads();
        int tslice = m0 / HWN, pin = m0 % HWN;     // BM=128 divides HWN: one t per CTA
        uint8_t* dst = (uint8_t*)outp + (size_t)tslice * CCH * HWN;
        #pragma unroll
        for (int i = 0; i < 4; ++i) {
            int idx = i * 256 + tid;
            int ci = idx >> 3, seg = idx & 7;
            uint4 val = *(const uint4*)(vts + ci * 144 + seg * 16);
            *(uint4*)(dst + (size_t)(n0 + ci) * HWN + pin + seg * 16) = val;
        }
    }
}

// =================== FP8 GEMM 128x128xBK64 e4m3, 3 stages, 2 CTAs/SM ============
// KTC: compile-time K-tile count (8 for K=512 -> fully unrolled; 64 for K=4096)
#define ROWB8 80
#define HSTG8 (BM * ROWB8)        // 10240
#define STG8  (2 * HSTG8)         // 20480
#define SMEM_PIPE8 (3 * STG8)     // 61440

__device__ __forceinline__ void load_tile8(uint32_t sm_base, const uint8_t* g,
                                           int ld, int row0, int k0, int tid)
{
    #pragma unroll
    for (int i = 0; i < 2; ++i) {
        int id  = i * 256 + tid;
        int row = id >> 2;
        int ch  = id & 3;
        cp16(sm_base + row * ROWB8 + ch * 16, g + (size_t)(row0 + row) * ld + k0 + ch * 16);
    }
}

#define FP8_ITER(it, KTC)                                                          \
    {                                                                              \
        cp_wait<1>();                                                              \
        __syncthreads();                                                           \
        if ((it) + 2 < (KTC)) {                                                    \
            int s = ((it) + 2) % 3;                                                \
            load_tile8(sb + s * STG8, A, (KTC) * BK, m0, ((it) + 2) * BK, tid);    \
            load_tile8(sb + s * STG8 + HSTG8, B, (KTC) * BK, n0, ((it) + 2) * BK, tid); \
        }                                                                          \
        CP_COMMIT();                                                               \
        const uint32_t as = sb + ((it) % 3) * STG8;                                \
        const uint32_t bs = as + HSTG8;                                            \
        _Pragma("unroll")                                                          \
        for (int kk = 0; kk < 2; ++kk) {                                           \
            uint32_t a[2][4], b[8][2];                                             \
            _Pragma("unroll")                                                      \
            for (int mt = 0; mt < 2; ++mt)                                         \
                ldsm_x4(a[mt][0], a[mt][1], a[mt][2], a[mt][3],                    \
                        as + a_off[mt] + kk * 32);                                 \
            _Pragma("unroll")                                                      \
            for (int np = 0; np < 4; ++np)                                         \
                ldsm_x4(b[np*2][0], b[np*2][1], b[np*2+1][0], b[np*2+1][1],        \
                        bs + b_off[np] + kk * 32);                                 \
            _Pragma("unroll")                                                      \
            for (int mt = 0; mt < 2; ++mt)                                         \
                _Pragma("unroll")                                                  \
                for (int nt = 0; nt < 8; ++nt)                                     \
                    mma16832(acc[mt][nt], a[mt], b[nt]);                           \
        }                                                                          \
    }

template<int KTC>
__global__ void __launch_bounds__(256, 2) gemm_fp8(
    const uint8_t* __restrict__ A, const uint8_t* __restrict__ B,
    __nv_bfloat16* __restrict__ C,
    int N, float scale, size_t sA, size_t sB, size_t sC)
{
    extern __shared__ __nv_bfloat16 smem[];
    const uint32_t sb = smem_u32(smem);
    const int tid = threadIdx.x, wid = tid >> 5, lane = tid & 31;
    const int m0 = blockIdx.y * BM, n0 = blockIdx.x * BN;
    const int z = blockIdx.z;
    A += (size_t)z * sA;
    B += (size_t)z * sB;
    C += (size_t)z * sC;

    const int wm = wid & 3, wn = wid >> 2;
    const int wrow = wm * 32, wcol = wn * 64;

    uint32_t a_off[2];
    #pragma unroll
    for (int mt = 0; mt < 2; ++mt)
        a_off[mt] = (wrow + mt * 16 + (lane & 15)) * ROWB8 + ((lane >> 4) << 4);
    uint32_t b_off[4];
    #pragma unroll
    for (int np = 0; np < 4; ++np) {
        int n = wcol + np * 16 + (lane & 7) + ((lane >> 4) << 3);
        b_off[np] = n * ROWB8 + (((lane >> 3) & 1) << 4);
    }

    float acc[2][8][4];
    #pragma unroll
    for (int i = 0; i < 2; ++i)
        #pragma unroll
        for (int j = 0; j < 8; ++j)
            #pragma unroll
            for (int q = 0; q < 4; ++q) acc[i][j][q] = 0.f;

    #pragma unroll
    for (int s = 0; s < 2; ++s) {
        load_tile8(sb + s * STG8, A, KTC * BK, m0, s * BK, tid);
        load_tile8(sb + s * STG8 + HSTG8, B, KTC * BK, n0, s * BK, tid);
        CP_COMMIT();
    }

    if (KTC <= 8) {
        #pragma unroll
        for (int it = 0; it < KTC; ++it) FP8_ITER(it, KTC)
    } else {
        for (int it = 0; it < KTC; ++it) FP8_ITER(it, KTC)
    }

    const int r_lane = lane >> 2, c_lane = (lane & 3) * 2;
    #pragma unroll
    for (int mt = 0; mt < 2; ++mt) {
        int r0 = m0 + wrow + mt * 16 + r_lane;
        #pragma unroll
        for (int nt = 0; nt < 8; ++nt) {
            int c = n0 + wcol + nt * 8 + c_lane;
            *(__nv_bfloat162*)(C + (size_t)r0 * N + c) =
                __floats2bfloat162_rn(acc[mt][nt][0] * scale, acc[mt][nt][1] * scale);
            *(__nv_bfloat162*)(C + (size_t)(r0 + 8) * N + c) =
                __floats2bfloat162_rn(acc[mt][nt][2] * scale, acc[mt][nt][3] * scale);
        }
    }
}

// =================== 128x128xBK64 bf16 GEMM with fused transpose+residual =======
__global__ void __launch_bounds__(256, 2) gemm_transadd(
    const __nv_bfloat16* __restrict__ A, const __nv_bfloat16* __restrict__ B,
    const float* __restrict__ bias, float* __restrict__ Cout,
    int K, const float* __restrict__ xres)
{
    extern __shared__ __nv_bfloat16 smem[];
    const uint32_t sb = smem_u32(smem);
    const int tid = threadIdx.x, wid = tid >> 5, lane = tid & 31;
    const int m0 = blockIdx.y * BM, n0 = blockIdx.x * BN;

    const int wm = wid & 3, wn = wid >> 2;
    const int wrow = wm * 32, wcol = wn * 64;
    const int KT = K / BK;

    uint32_t a_off[2];
    #pragma unroll
    for (int mt = 0; mt < 2; ++mt)
        a_off[mt] = (wrow + mt * 16 + (lane & 15)) * ROWB + ((lane >> 4) << 4);
    uint32_t b_off[4];
    #pragma unroll
    for (int np = 0; np < 4; ++np) {
        int n  = wcol + np * 16 + (lane & 7) + ((lane >> 4) << 3);
        int kf = ((lane >> 3) & 1) << 3;
        b_off[np] = n * ROWB + kf * 2;
    }

    float acc[2][8][4];
    #pragma unroll
    for (int i = 0; i < 2; ++i)
        #pragma unroll
        for (int j = 0; j < 8; ++j)
            #pragma unroll
            for (int q = 0; q < 4; ++q) acc[i][j][q] = 0.f;

    #pragma unroll
    for (int s = 0; s < 2; ++s) {
        load_tile64(sb + s * STG, A, K, m0, s * BK, tid);
        load_tile64(sb + s * STG + HSTG, B, K, n0, s * BK, tid);
        CP_COMMIT();
    }

    for (int it = 0; it < KT; ++it) {
        cp_wait<1>();
        __syncthreads();
        if (it + 2 < KT) {
            int s = (it + 2) % 3;
            load_tile64(sb + s * STG, A, K, m0, (it + 2) * BK, tid);
            load_tile64(sb + s * STG + HSTG, B, K, n0, (it + 2) * BK, tid);
        }
        CP_COMMIT();

        const uint32_t as = sb + (it % 3) * STG;
        const uint32_t bs = as + HSTG;
        #pragma unroll
        for (int kk = 0; kk < 4; ++kk) {
            uint32_t a[2][4], b[8][2];
            #pragma unroll
            for (int mt = 0; mt < 2; ++mt)
                ldsm_x4(a[mt][0], a[mt][1], a[mt][2], a[mt][3], as + a_off[mt] + kk * 32);
            #pragma unroll
            for (int np = 0; np < 4; ++np)
                ldsm_x4(b[np*2][0], b[np*2][1], b[np*2+1][0], b[np*2+1][1],
                        bs + b_off[np] + kk * 32);
            #pragma unroll
            for (int mt = 0; mt < 2; ++mt)
                #pragma unroll
                for (int nt = 0; nt < 8; ++nt)
                    mma16816(acc[mt][nt], a[mt], b[nt]);
        }
    }

    const int r_lane = lane >> 2, c_lane = (lane & 3) * 2;
    __syncthreads();
    float* st = (float*)smem;
    #pragma unroll
    for (int mt = 0; mt < 2; ++mt) {
        int rl = wrow + mt * 16 + r_lane;
        #pragma unroll
        for (int nt = 0; nt < 8; ++nt) {
            int cl = wcol + nt * 8 + c_lane;
            float b0 = bias[n0 + cl], b1 = bias[n0 + cl + 1];
            st[rl * 129 + cl]           = acc[mt][nt][0] + b0;
            st[rl * 129 + cl + 1]       = acc[mt][nt][1] + b1;
            st[(rl + 8) * 129 + cl]     = acc[mt][nt][2] + b0;
            st[(rl + 8) * 129 + cl + 1] = acc[mt][nt][3] + b1;
        }
    }
    __syncthreads();
    #pragma unroll
    for (int i = 0; i < 64; ++i) {
        int idx = i * 256 + tid;
        int ci = idx >> 7, pi = idx & 127;
        size_t gi = (size_t)(n0 + ci) * PN + (m0 + pi);
        Cout[gi] = xres[gi] + st[pi * 129 + ci];
    }
}

// ---------------- softmax: bf16 scores -> fp8 probs (x256) ----------------------
__global__ void __launch_bounds__(256) softmax8(const __nv_bfloat16* __restrict__ P,
                                                uint8_t* __restrict__ P8)
{
    __shared__ float redm[8], reds[8];
    const uint4* row = (const uint4*)(P + (size_t)blockIdx.x * HWN);
    uint4 d[2];
    float f[16];
    d[0] = row[threadIdx.x];
    d[1] = row[threadIdx.x + 256];
    #pragma unroll
    for (int j = 0; j < 2; ++j) {
        const __nv_bfloat162* h = (const __nv_bfloat162*)&d[j];
        #pragma unroll
        for (int q = 0; q < 4; ++q) {
            float2 t = __bfloat1622float2(h[q]);
            f[j * 8 + q * 2] = t.x; f[j * 8 + q * 2 + 1] = t.y;
        }
    }

    float m = -3.4e38f;
    #pragma unroll
    for (int i = 0; i < 16; ++i) m = fmaxf(m, f[i]);
    #pragma unroll
    for (int o = 16; o > 0; o >>= 1) m = fmaxf(m, __shfl_xor_sync(0xffffffffu, m, o));
    int wid = threadIdx.x >> 5, lane = threadIdx.x & 31;
    if (lane == 0) redm[wid] = m;
    __syncthreads();
    if (wid == 0) {
        float t = (lane < 8) ? redm[lane] : -3.4e38f;
        #pragma unroll
        for (int o = 16; o > 0; o >>= 1) t = fmaxf(t, __shfl_xor_sync(0xffffffffu, t, o));
        if (lane == 0) redm[0] = t;
    }
    __syncthreads();
    m = redm[0];

    float s = 0.f;
    #pragma unroll
    for (int i = 0; i < 16; ++i) { f[i] = fexp(f[i] - m); s += f[i]; }
    #pragma unroll
    for (int o = 16; o > 0; o >>= 1) s += __shfl_xor_sync(0xffffffffu, s, o);
    if (lane == 0) reds[wid] = s;
    __syncthreads();
    if (wid == 0) {
        float t = (lane < 8) ? reds[lane] : 0.f;
        #pragma unroll
        for (int o = 16; o > 0; o >>= 1) t += __shfl_xor_sync(0xffffffffu, t, o);
        if (lane == 0) reds[0] = t;
    }
    __syncthreads();
    float inv = 256.f / reds[0];     // x256 so probs live in e4m3 normal range

    uint8_t* p8row = P8 + (size_t)blockIdx.x * HWN;
    #pragma unroll
    for (int j = 0; j < 2; ++j) {
        uint16_t w[4];
        #pragma unroll
        for (int q = 0; q < 4; ++q)
            w[q] = fp8x2(f[j * 8 + q * 2] * inv, f[j * 8 + q * 2 + 1] * inv);
        uint2 outv;
        outv.x = (uint32_t)w[0] | ((uint32_t)w[1] << 16);
        outv.y = (uint32_t)w[2] | ((uint32_t)w[3] << 16);
        *(uint2*)(p8row + (threadIdx.x + j * 256) * 8) = outv;
    }
}

// ---------------- launch ---------------------------------------------------------
extern "C" void kernel_launch(void* const* d_in, const int* in_sizes, int n_in,
                              void* d_out, int out_size)
{
    const float* x     = (const float*)d_in[0];
    const float* gamma = (const float*)d_in[1];
    const float* beta  = (const float*)d_in[2];
    const float* wq    = (const float*)d_in[3];
    const float* bq    = (const float*)d_in[4];
    const float* wk    = (const float*)d_in[5];
    const float* bk    = (const float*)d_in[6];
    const float* wv    = (const float*)d_in[7];
    const float* bv    = (const float*)d_in[8];
    const float* wp    = (const float*)d_in[9];
    const float* bp    = (const float*)d_in[10];
    float* out = (float*)d_out;

    __nv_bfloat16 *hl, *o, *P, *wt;
    uint8_t *q8, *k8, *vt8, *P8;
    cudaGetSymbolAddress((void**)&hl, g_hl);
    cudaGetSymbolAddress((void**)&q8, g_q8);
    cudaGetSymbolAddress((void**)&k8, g_k8);
    cudaGetSymbolAddress((void**)&vt8, g_vt8);
    cudaGetSymbolAddress((void**)&o,  g_o);
    cudaGetSymbolAddress((void**)&P,  g_P);
    cudaGetSymbolAddress((void**)&P8, g_P8);
    cudaGetSymbolAddress((void**)&wt, g_wt);

    cudaFuncSetAttribute(gemm_qkv,      cudaFuncAttributeMaxDynamicSharedMemorySize, SMEM_PIPE);
    cudaFuncSetAttribute(gemm_fp8<8>,   cudaFuncAttributeMaxDynamicSharedMemorySize, SMEM_PIPE8);
    cudaFuncSetAttribute(gemm_fp8<64>,  cudaFuncAttributeMaxDynamicSharedMemorySize, SMEM_PIPE8);
    cudaFuncSetAttribute(gemm_transadd, cudaFuncAttributeMaxDynamicSharedMemorySize, SMEM_PIPE);

    dim3 tb(32, 32);

    gn_stats<<<GROUPS, 512>>>(x);
    norm_transpose<<<dim3(PN / 32, CCH / 32), tb>>>(x, gamma, beta, hl);

    W4 ws = { { wq, wk, wv, wp } };
    wtrans4<<<dim3(16, 16, 4), tb>>>(ws, wt);

    // fused q/k/v projections: q,k -> fp8 row-major; v -> fp8 transposed (vt8)
    Ptr3 qkv = { bq, bk, bv, q8, k8, vt8 };
    gemm_qkv<<<dim3(CCH / BN, PN / BM, 3), 256, SMEM_PIPE>>>(hl, wt, CCH, CCH, qkv);

    const float scale = 0.044194173824159216f;  // 512^-0.5

    // scores: fp8 GEMM (K=512, fully unrolled), bf16 out, batched over 8 t-slices
    gemm_fp8<8><<<dim3(HWN / BN, HWN / BM, TT), 256, SMEM_PIPE8>>>(
        q8, k8, P, HWN, scale,
        (size_t)HWN * CCH, (size_t)HWN * CCH, (size_t)HWN * HWN);

    softmax8<<<TT * HWN, 256>>>(P, P8);

    // PV: fp8 GEMM (K=4096), o = (P8 @ vt8^T) / 256
    gemm_fp8<64><<<dim3(CCH / BN, HWN / BM, TT), 256, SMEM_PIPE8>>>(
        P8, vt8, o, CCH, 1.f / 256.f,
        (size_t)HWN * HWN, (size_t)CCH * HWN, (size_t)HWN * CCH);

    // output projection with fused transpose + residual (bf16)
    gemm_transadd<<<dim3(CCH / BN, PN / BM, 1), 256, SMEM_PIPE>>>(
        o, wt + 3 * CCH * CCH, bp, out, CCH, x);
}

// round 17
// speedup vs baseline: 1.6091x; 1.0107x over previous
#include <cuda_runtime.h>
#include <cuda_bf16.h>
#include <math.h>
#include <stdint.h>

#define CCH   512
#define TT    8
#define HWN   4096
#define PN    (TT*HWN)
#define GROUPS 32
#define GSIZE (16*PN)

// ---------------- scratch (device globals) ----------------------------------
__device__ float g_mean[GROUPS];
__device__ float g_rstd[GROUPS];
__device__ __nv_bfloat16 g_hl[(size_t)PN * CCH];
__device__ uint8_t       g_q8[(size_t)PN * CCH];
__device__ uint8_t       g_k8[(size_t)PN * CCH];
__device__ uint8_t       g_vt8[(size_t)PN * CCH];
__device__ __nv_bfloat16 g_o [(size_t)PN * CCH];
__device__ __nv_bfloat16 g_P [(size_t)TT * HWN * HWN];   // 256 MB scores (bf16)
__device__ uint8_t       g_P8[(size_t)TT * HWN * HWN];   // 128 MB probs (e4m3 x256)
__device__ __nv_bfloat16 g_wt[4 * CCH * CCH];

struct Ptr3 {
    const float* b0; const float* b1; const float* b2;
    void* o0; void* o1; void* o2;
};
struct W4 { const float* w[4]; };

// ---------------- PTX helpers -------------------------------------------------
__device__ __forceinline__ uint32_t smem_u32(const void* p) {
    uint32_t a;
    asm("{ .reg .u64 t; cvta.to.shared.u64 t, %1; cvt.u32.u64 %0, t; }" : "=r"(a) : "l"(p));
    return a;
}
__device__ __forceinline__ void ldsm_x4(uint32_t& r0, uint32_t& r1, uint32_t& r2,
                                        uint32_t& r3, uint32_t addr) {
    asm volatile("ldmatrix.sync.aligned.m8n8.x4.shared.b16 {%0,%1,%2,%3}, [%4];"
                 : "=r"(r0), "=r"(r1), "=r"(r2), "=r"(r3) : "r"(addr));
}
__device__ __forceinline__ void mma16816(float* d, const uint32_t* a, const uint32_t* b) {
    asm volatile("mma.sync.aligned.m16n8k16.row.col.f32.bf16.bf16.f32 "
                 "{%0,%1,%2,%3}, {%4,%5,%6,%7}, {%8,%9}, {%0,%1,%2,%3};"
                 : "+f"(d[0]), "+f"(d[1]), "+f"(d[2]), "+f"(d[3])
                 : "r"(a[0]), "r"(a[1]), "r"(a[2]), "r"(a[3]), "r"(b[0]), "r"(b[1]));
}
__device__ __forceinline__ void mma16832(float* d, const uint32_t* a, const uint32_t* b) {
    asm volatile("mma.sync.aligned.m16n8k32.row.col.f32.e4m3.e4m3.f32 "
                 "{%0,%1,%2,%3}, {%4,%5,%6,%7}, {%8,%9}, {%0,%1,%2,%3};"
                 : "+f"(d[0]), "+f"(d[1]), "+f"(d[2]), "+f"(d[3])
                 : "r"(a[0]), "r"(a[1]), "r"(a[2]), "r"(a[3]), "r"(b[0]), "r"(b[1]));
}
__device__ __forceinline__ void cp16(uint32_t sm, const void* gp) {
    asm volatile("cp.async.cg.shared.global [%0], [%1], 16;" :: "r"(sm), "l"(gp) : "memory");
}
#define CP_COMMIT() asm volatile("cp.async.commit_group;" ::: "memory")
template<int W> __device__ __forceinline__ void cp_wait() {
    asm volatile("cp.async.wait_group %0;" :: "n"(W) : "memory");
}
// packed fp8 convert: lower byte = lo, upper = hi
__device__ __forceinline__ uint16_t fp8x2(float lo, float hi) {
    uint16_t r;
    asm("cvt.rn.satfinite.e4m3x2.f32 %0, %1, %2;" : "=h"(r) : "f"(hi), "f"(lo));
    return r;
}

// FMA-only exp
__device__ __forceinline__ float fexp(float x) {
    float y = fmaxf(x * 1.44269504f, -120.f);
    float n = rintf(y);
    float f = y - n;
    float p = 0.00133336f;
    p = fmaf(p, f, 0.00961813f);
    p = fmaf(p, f, 0.05550411f);
    p = fmaf(p, f, 0.24022651f);
    p = fmaf(p, f, 0.69314718f);
    p = fmaf(p, f, 1.0f);
    return __int_as_float(__float_as_int(p) + (((int)n) << 23));
}

// ---------------- group-norm stats --------------------------------------------
__global__ void __launch_bounds__(512) gn_stats(const float* __restrict__ x) {
    int g = blockIdx.x;
    const float4* p = (const float4*)(x + (size_t)g * GSIZE);
    float s = 0.f, ss = 0.f;
    for (int i = threadIdx.x; i < GSIZE / 4; i += 512) {
        float4 v = p[i];
        s  += v.x + v.y + v.z + v.w;
        ss += v.x * v.x + v.y * v.y + v.z * v.z + v.w * v.w;
    }
    __shared__ float shs[512], shq[512];
    shs[threadIdx.x] = s; shq[threadIdx.x] = ss;
    __syncthreads();
    for (int st = 256; st > 0; st >>= 1) {
        if (threadIdx.x < st) {
            shs[threadIdx.x] += shs[threadIdx.x + st];
            shq[threadIdx.x] += shq[threadIdx.x + st];
        }
        __syncthreads();
    }
    if (threadIdx.x == 0) {
        float m = shs[0] / (float)GSIZE;
        float var = shq[0] / (float)GSIZE - m * m;
        g_mean[g] = m;
        g_rstd[g] = rsqrtf(var + 1e-6f);
    }
}

// ---------------- normalize + transpose to channels-last (bf16) ---------------
__global__ void __launch_bounds__(1024) norm_transpose(
    const float* __restrict__ x, const float* __restrict__ gamma,
    const float* __restrict__ beta, __nv_bfloat16* __restrict__ hl)
{
    __shared__ float tile[32][33];
    int p0 = blockIdx.x * 32, c0 = blockIdx.y * 32;
    int c = c0 + threadIdx.y;
    tile[threadIdx.y][threadIdx.x] = x[(size_t)c * PN + p0 + threadIdx.x];
    __syncthreads();
    int cc = c0 + threadIdx.x;
    int g = cc >> 4;
    float a = gamma[cc] * g_rstd[g];
    float b = beta[cc] - g_mean[g] * a;
    hl[(size_t)(p0 + threadIdx.y) * CCH + cc] =
        __float2bfloat16(tile[threadIdx.x][threadIdx.y] * a + b);
}

// ---------------- batched weight transpose fp32 [K][N] -> bf16 [N][K] ----------
__global__ void __launch_bounds__(1024) wtrans4(W4 ws, __nv_bfloat16* __restrict__ Wt)
{
    __shared__ float t[32][33];
    const float* W = ws.w[blockIdx.z];
    __nv_bfloat16* Wo = Wt + (size_t)blockIdx.z * CCH * CCH;
    int k0 = blockIdx.y * 32, n0 = blockIdx.x * 32;
    t[threadIdx.y][threadIdx.x] = W[(size_t)(k0 + threadIdx.y) * CCH + n0 + threadIdx.x];
    __syncthreads();
    Wo[(size_t)(n0 + threadIdx.y) * CCH + k0 + threadIdx.x] =
        __float2bfloat16(t[threadIdx.x][threadIdx.y]);
}

// =================== bf16 GEMM 128x128xBK64, K=512 fully unrolled ================
#define BK   64
#define ROWB 144
#define BM 128
#define BN 128
#define KT5  8                     // K=512 / BK
#define HSTG (BM * ROWB)          // 18432
#define STG  (2 * HSTG)           // 36864
#define SMEM_PIPE (3 * STG)       // 110592

__device__ __forceinline__ void load_tile64(uint32_t sm_base, const __nv_bfloat16* g,
                                            int ld, int row0, int k0, int tid)
{
    #pragma unroll
    for (int i = 0; i < 4; ++i) {
        int id  = i * 256 + tid;
        int row = id >> 3;
        int ch  = id & 7;
        cp16(sm_base + row * ROWB + ch * 16, g + (size_t)(row0 + row) * ld + k0 + ch * 8);
    }
}

#define BF16_ITER(it, KTC, Amat, Bmat, LD)                                         \
    {                                                                              \
        cp_wait<1>();                                                              \
        __syncthreads();                                                           \
        if ((it) + 2 < (KTC)) {                                                    \
            int s = ((it) + 2) % 3;                                                \
            load_tile64(sb + s * STG, Amat, LD, m0, ((it) + 2) * BK, tid);         \
            load_tile64(sb + s * STG + HSTG, Bmat, LD, n0, ((it) + 2) * BK, tid);  \
        }                                                                          \
        CP_COMMIT();                                                               \
        const uint32_t as = sb + ((it) % 3) * STG;                                 \
        const uint32_t bs = as + HSTG;                                             \
        _Pragma("unroll")                                                          \
        for (int kk = 0; kk < 4; ++kk) {                                           \
            uint32_t a[2][4], b[8][2];                                             \
            _Pragma("unroll")                                                      \
            for (int mt = 0; mt < 2; ++mt)                                         \
                ldsm_x4(a[mt][0], a[mt][1], a[mt][2], a[mt][3],                    \
                        as + a_off[mt] + kk * 32);                                 \
            _Pragma("unroll")                                                      \
            for (int np = 0; np < 4; ++np)                                         \
                ldsm_x4(b[np*2][0], b[np*2][1], b[np*2+1][0], b[np*2+1][1],        \
                        bs + b_off[np] + kk * 32);                                 \
            _Pragma("unroll")                                                      \
            for (int mt = 0; mt < 2; ++mt)                                         \
                _Pragma("unroll")                                                  \
                for (int nt = 0; nt < 8; ++nt)                                     \
                    mma16816(acc[mt][nt], a[mt], b[nt]);                           \
        }                                                                          \
    }

// z in {0,1}: q,k -> fp8 row-major. z==2: v -> fp8 transposed (vt8[t][c][p]).
__global__ void __launch_bounds__(256, 2) gemm_qkv(
    const __nv_bfloat16* __restrict__ A, const __nv_bfloat16* __restrict__ B,
    int N, Ptr3 p3)
{
    extern __shared__ __nv_bfloat16 smem[];
    const uint32_t sb = smem_u32(smem);
    const int tid = threadIdx.x, wid = tid >> 5, lane = tid & 31;
    const int m0 = blockIdx.y * BM, n0 = blockIdx.x * BN;
    const int z = blockIdx.z;

    B += (size_t)z * (CCH * CCH);
    const float* bias_p = (z == 0) ? p3.b0 : (z == 1) ? p3.b1 : p3.b2;
    void* outp          = (z == 0) ? p3.o0 : (z == 1) ? p3.o1 : p3.o2;

    const int wm = wid & 3, wn = wid >> 2;
    const int wrow = wm * 32, wcol = wn * 64;

    uint32_t a_off[2];
    #pragma unroll
    for (int mt = 0; mt < 2; ++mt)
        a_off[mt] = (wrow + mt * 16 + (lane & 15)) * ROWB + ((lane >> 4) << 4);
    uint32_t b_off[4];
    #pragma unroll
    for (int np = 0; np < 4; ++np) {
        int n  = wcol + np * 16 + (lane & 7) + ((lane >> 4) << 3);
        int kf = ((lane >> 3) & 1) << 3;
        b_off[np] = n * ROWB + kf * 2;
    }

    float acc[2][8][4];
    #pragma unroll
    for (int i = 0; i < 2; ++i)
        #pragma unroll
        for (int j = 0; j < 8; ++j)
            #pragma unroll
            for (int q = 0; q < 4; ++q) acc[i][j][q] = 0.f;

    #pragma unroll
    for (int s = 0; s < 2; ++s) {
        load_tile64(sb + s * STG, A, CCH, m0, s * BK, tid);
        load_tile64(sb + s * STG + HSTG, B, CCH, n0, s * BK, tid);
        CP_COMMIT();
    }

    #pragma unroll
    for (int it = 0; it < KT5; ++it) BF16_ITER(it, KT5, A, B, CCH)

    const int r_lane = lane >> 2, c_lane = (lane & 3) * 2;

    if (z != 2) {
        uint8_t* Cb = (uint8_t*)outp;
        #pragma unroll
        for (int mt = 0; mt < 2; ++mt) {
            int r0 = m0 + wrow + mt * 16 + r_lane;
            #pragma unroll
            for (int nt = 0; nt < 8; ++nt) {
                int c = n0 + wcol + nt * 8 + c_lane;
                float b0 = bias_p[c], b1 = bias_p[c + 1];
                *(uint16_t*)(Cb + (size_t)r0 * N + c) =
                    fp8x2(acc[mt][nt][0] + b0, acc[mt][nt][1] + b1);
                *(uint16_t*)(Cb + (size_t)(r0 + 8) * N + c) =
                    fp8x2(acc[mt][nt][2] + b0, acc[mt][nt][3] + b1);
            }
        }
    } else {
        // v: transposed fp8 [t][c][p] via smem staging
        cp_wait<0>();
        __syncthreads();
        uint8_t* vts = (uint8_t*)smem;
        #pragma unroll
        for (int mt = 0; mt < 2; ++mt) {
            int rl = wrow + mt * 16 + r_lane;
            #pragma unroll
            for (int nt = 0; nt < 8; ++nt) {
                int cl = wcol + nt * 8 + c_lane;
                float b0 = bias_p[n0 + cl], b1 = bias_p[n0 + cl + 1];
                uint16_t wlo = fp8x2(acc[mt][nt][0] + b0, acc[mt][nt][1] + b1);
                uint16_t whi = fp8x2(acc[mt][nt][2] + b0, acc[mt][nt][3] + b1);
                vts[cl * 144 + rl]           = (uint8_t)(wlo & 0xFF);
                vts[(cl + 1) * 144 + rl]     = (uint8_t)(wlo >> 8);
                vts[cl * 144 + rl + 8]       = (uint8_t)(whi & 0xFF);
                vts[(cl + 1) * 144 + rl + 8] = (uint8_t)(whi >> 8);
            }
        }
        __syncthreads();
        int tslice = m0 / HWN, pin = m0 % HWN;
        uint8_t* dst = (uint8_t*)outp + (size_t)tslice * CCH * HWN;
        #pragma unroll
        for (int i = 0; i < 4; ++i) {
            int idx = i * 256 + tid;
            int ci = idx >> 3, seg = idx & 7;
            uint4 val = *(const uint4*)(vts + ci * 144 + seg * 16);
            *(uint4*)(dst + (size_t)(n0 + ci) * HWN + pin + seg * 16) = val;
        }
    }
}

// =================== FP8 GEMM 128x128xBK64 e4m3, 3 stages, 2 CTAs/SM ============
#define ROWB8 80
#define HSTG8 (BM * ROWB8)        // 10240
#define STG8  (2 * HSTG8)         // 20480
#define SMEM_PIPE8 (3 * STG8)     // 61440

__device__ __forceinline__ void load_tile8(uint32_t sm_base, const uint8_t* g,
                                           int ld, int row0, int k0, int tid)
{
    #pragma unroll
    for (int i = 0; i < 2; ++i) {
        int id  = i * 256 + tid;
        int row = id >> 2;
        int ch  = id & 3;
        cp16(sm_base + row * ROWB8 + ch * 16, g + (size_t)(row0 + row) * ld + k0 + ch * 16);
    }
}

#define FP8_ITER(it, KTC)                                                          \
    {                                                                              \
        cp_wait<1>();                                                              \
        __syncthreads();                                                           \
        if ((it) + 2 < (KTC)) {                                                    \
            int s = ((it) + 2) % 3;                                                \
            load_tile8(sb + s * STG8, A, (KTC) * BK, m0, ((it) + 2) * BK, tid);    \
            load_tile8(sb + s * STG8 + HSTG8, B, (KTC) * BK, n0, ((it) + 2) * BK, tid); \
        }                                                                          \
        CP_COMMIT();                                                               \
        const uint32_t as = sb + ((it) % 3) * STG8;                                \
        const uint32_t bs = as + HSTG8;                                            \
        _Pragma("unroll")                                                          \
        for (int kk = 0; kk < 2; ++kk) {                                           \
            uint32_t a[2][4], b[8][2];                                             \
            _Pragma("unroll")                                                      \
            for (int mt = 0; mt < 2; ++mt)                                         \
                ldsm_x4(a[mt][0], a[mt][1], a[mt][2], a[mt][3],                    \
                        as + a_off[mt] + kk * 32);                                 \
            _Pragma("unroll")                                                      \
            for (int np = 0; np < 4; ++np)                                         \
                ldsm_x4(b[np*2][0], b[np*2][1], b[np*2+1][0], b[np*2+1][1],        \
                        bs + b_off[np] + kk * 32);                                 \
            _Pragma("unroll")                                                      \
            for (int mt = 0; mt < 2; ++mt)                                         \
                _Pragma("unroll")                                                  \
                for (int nt = 0; nt < 8; ++nt)                                     \
                    mma16832(acc[mt][nt], a[mt], b[nt]);                           \
        }                                                                          \
    }

template<int KTC>
__global__ void __launch_bounds__(256, 2) gemm_fp8(
    const uint8_t* __restrict__ A, const uint8_t* __restrict__ B,
    __nv_bfloat16* __restrict__ C,
    int N, float scale, size_t sA, size_t sB, size_t sC)
{
    extern __shared__ __nv_bfloat16 smem[];
    const uint32_t sb = smem_u32(smem);
    const int tid = threadIdx.x, wid = tid >> 5, lane = tid & 31;
    const int m0 = blockIdx.y * BM, n0 = blockIdx.x * BN;
    const int z = blockIdx.z;
    A += (size_t)z * sA;
    B += (size_t)z * sB;
    C += (size_t)z * sC;

    const int wm = wid & 3, wn = wid >> 2;
    const int wrow = wm * 32, wcol = wn * 64;

    uint32_t a_off[2];
    #pragma unroll
    for (int mt = 0; mt < 2; ++mt)
        a_off[mt] = (wrow + mt * 16 + (lane & 15)) * ROWB8 + ((lane >> 4) << 4);
    uint32_t b_off[4];
    #pragma unroll
    for (int np = 0; np < 4; ++np) {
        int n = wcol + np * 16 + (lane & 7) + ((lane >> 4) << 3);
        b_off[np] = n * ROWB8 + (((lane >> 3) & 1) << 4);
    }

    float acc[2][8][4];
    #pragma unroll
    for (int i = 0; i < 2; ++i)
        #pragma unroll
        for (int j = 0; j < 8; ++j)
            #pragma unroll
            for (int q = 0; q < 4; ++q) acc[i][j][q] = 0.f;

    #pragma unroll
    for (int s = 0; s < 2; ++s) {
        load_tile8(sb + s * STG8, A, KTC * BK, m0, s * BK, tid);
        load_tile8(sb + s * STG8 + HSTG8, B, KTC * BK, n0, s * BK, tid);
        CP_COMMIT();
    }

    if (KTC <= 8) {
        #pragma unroll
        for (int it = 0; it < KTC; ++it) FP8_ITER(it, KTC)
    } else {
        for (int it = 0; it < KTC; ++it) FP8_ITER(it, KTC)
    }

    const int r_lane = lane >> 2, c_lane = (lane & 3) * 2;
    #pragma unroll
    for (int mt = 0; mt < 2; ++mt) {
        int r0 = m0 + wrow + mt * 16 + r_lane;
        #pragma unroll
        for (int nt = 0; nt < 8; ++nt) {
            int c = n0 + wcol + nt * 8 + c_lane;
            *(__nv_bfloat162*)(C + (size_t)r0 * N + c) =
                __floats2bfloat162_rn(acc[mt][nt][0] * scale, acc[mt][nt][1] * scale);
            *(__nv_bfloat162*)(C + (size_t)(r0 + 8) * N + c) =
                __floats2bfloat162_rn(acc[mt][nt][2] * scale, acc[mt][nt][3] * scale);
        }
    }
}

// ============ 128x128 bf16 GEMM (K=512 unrolled) with fused transpose+residual ===
__global__ void __launch_bounds__(256, 2) gemm_transadd(
    const __nv_bfloat16* __restrict__ A, const __nv_bfloat16* __restrict__ B,
    const float* __restrict__ bias, float* __restrict__ Cout,
    const float* __restrict__ xres)
{
    extern __shared__ __nv_bfloat16 smem[];
    const uint32_t sb = smem_u32(smem);
    const int tid = threadIdx.x, wid = tid >> 5, lane = tid & 31;
    const int m0 = blockIdx.y * BM, n0 = blockIdx.x * BN;

    const int wm = wid & 3, wn = wid >> 2;
    const int wrow = wm * 32, wcol = wn * 64;

    uint32_t a_off[2];
    #pragma unroll
    for (int mt = 0; mt < 2; ++mt)
        a_off[mt] = (wrow + mt * 16 + (lane & 15)) * ROWB + ((lane >> 4) << 4);
    uint32_t b_off[4];
    #pragma unroll
    for (int np = 0; np < 4; ++np) {
        int n  = wcol + np * 16 + (lane & 7) + ((lane >> 4) << 3);
        int kf = ((lane >> 3) & 1) << 3;
        b_off[np] = n * ROWB + kf * 2;
    }

    float acc[2][8][4];
    #pragma unroll
    for (int i = 0; i < 2; ++i)
        #pragma unroll
        for (int j = 0; j < 8; ++j)
            #pragma unroll
            for (int q = 0; q < 4; ++q) acc[i][j][q] = 0.f;

    #pragma unroll
    for (int s = 0; s < 2; ++s) {
        load_tile64(sb + s * STG, A, CCH, m0, s * BK, tid);
        load_tile64(sb + s * STG + HSTG, B, CCH, n0, s * BK, tid);
        CP_COMMIT();
    }

    #pragma unroll
    for (int it = 0; it < KT5; ++it) BF16_ITER(it, KT5, A, B, CCH)

    const int r_lane = lane >> 2, c_lane = (lane & 3) * 2;
    __syncthreads();
    float* st = (float*)smem;
    #pragma unroll
    for (int mt = 0; mt < 2; ++mt) {
        int rl = wrow + mt * 16 + r_lane;
        #pragma unroll
        for (int nt = 0; nt < 8; ++nt) {
            int cl = wcol + nt * 8 + c_lane;
            float b0 = bias[n0 + cl], b1 = bias[n0 + cl + 1];
            st[rl * 129 + cl]           = acc[mt][nt][0] + b0;
            st[rl * 129 + cl + 1]       = acc[mt][nt][1] + b1;
            st[(rl + 8) * 129 + cl]     = acc[mt][nt][2] + b0;
            st[(rl + 8) * 129 + cl + 1] = acc[mt][nt][3] + b1;
        }
    }
    __syncthreads();
    #pragma unroll
    for (int i = 0; i < 64; ++i) {
        int idx = i * 256 + tid;
        int ci = idx >> 7, pi = idx & 127;
        size_t gi = (size_t)(n0 + ci) * PN + (m0 + pi);
        Cout[gi] = xres[gi] + st[pi * 129 + ci];
    }
}

// ---------------- softmax: bf16 scores -> fp8 probs (x256) ----------------------
__global__ void __launch_bounds__(256) softmax8(const __nv_bfloat16* __restrict__ P,
                                                uint8_t* __restrict__ P8)
{
    __shared__ float redm[8], reds[8];
    const uint4* row = (const uint4*)(P + (size_t)blockIdx.x * HWN);
    uint4 d[2];
    float f[16];
    d[0] = row[threadIdx.x];
    d[1] = row[threadIdx.x + 256];
    #pragma unroll
    for (int j = 0; j < 2; ++j) {
        const __nv_bfloat162* h = (const __nv_bfloat162*)&d[j];
        #pragma unroll
        for (int q = 0; q < 4; ++q) {
            float2 t = __bfloat1622float2(h[q]);
            f[j * 8 + q * 2] = t.x; f[j * 8 + q * 2 + 1] = t.y;
        }
    }

    float m = -3.4e38f;
    #pragma unroll
    for (int i = 0; i < 16; ++i) m = fmaxf(m, f[i]);
    #pragma unroll
    for (int o = 16; o > 0; o >>= 1) m = fmaxf(m, __shfl_xor_sync(0xffffffffu, m, o));
    int wid = threadIdx.x >> 5, lane = threadIdx.x & 31;
    if (lane == 0) redm[wid] = m;
    __syncthreads();
    if (wid == 0) {
        float t = (lane < 8) ? redm[lane] : -3.4e38f;
        #pragma unroll
        for (int o = 16; o > 0; o >>= 1) t = fmaxf(t, __shfl_xor_sync(0xffffffffu, t, o));
        if (lane == 0) redm[0] = t;
    }
    __syncthreads();
    m = redm[0];

    float s = 0.f;
    #pragma unroll
    for (int i = 0; i < 16; ++i) { f[i] = fexp(f[i] - m); s += f[i]; }
    #pragma unroll
    for (int o = 16; o > 0; o >>= 1) s += __shfl_xor_sync(0xffffffffu, s, o);
    if (lane == 0) reds[wid] = s;
    __syncthreads();
    if (wid == 0) {
        float t = (lane < 8) ? reds[lane] : 0.f;
        #pragma unroll
        for (int o = 16; o > 0; o >>= 1) t += __shfl_xor_sync(0xffffffffu, t, o);
        if (lane == 0) reds[0] = t;
    }
    __syncthreads();
    float inv = 256.f / reds[0];     // x256 so probs live in e4m3 normal range

    uint8_t* p8row = P8 + (size_t)blockIdx.x * HWN;
    #pragma unroll
    for (int j = 0; j < 2; ++j) {
        uint16_t w[4];
        #pragma unroll
        for (int q = 0; q < 4; ++q)
            w[q] = fp8x2(f[j * 8 + q * 2] * inv, f[j * 8 + q * 2 + 1] * inv);
        uint2 outv;
        outv.x = (uint32_t)w[0] | ((uint32_t)w[1] << 16);
        outv.y = (uint32_t)w[2] | ((uint32_t)w[3] << 16);
        *(uint2*)(p8row + (threadIdx.x + j * 256) * 8) = outv;
    }
}

// ---------------- launch ---------------------------------------------------------
extern "C" void kernel_launch(void* const* d_in, const int* in_sizes, int n_in,
                              void* d_out, int out_size)
{
    const float* x     = (const float*)d_in[0];
    const float* gamma = (const float*)d_in[1];
    const float* beta  = (const float*)d_in[2];
    const float* wq    = (const float*)d_in[3];
    const float* bq    = (const float*)d_in[4];
    const float* wk    = (const float*)d_in[5];
    const float* bk    = (const float*)d_in[6];
    const float* wv    = (const float*)d_in[7];
    const float* bv    = (const float*)d_in[8];
    const float* wp    = (const float*)d_in[9];
    const float* bp    = (const float*)d_in[10];
    float* out = (float*)d_out;

    __nv_bfloat16 *hl, *o, *P, *wt;
    uint8_t *q8, *k8, *vt8, *P8;
    cudaGetSymbolAddress((void**)&hl, g_hl);
    cudaGetSymbolAddress((void**)&q8, g_q8);
    cudaGetSymbolAddress((void**)&k8, g_k8);
    cudaGetSymbolAddress((void**)&vt8, g_vt8);
    cudaGetSymbolAddress((void**)&o,  g_o);
    cudaGetSymbolAddress((void**)&P,  g_P);
    cudaGetSymbolAddress((void**)&P8, g_P8);
    cudaGetSymbolAddress((void**)&wt, g_wt);

    cudaFuncSetAttribute(gemm_qkv,      cudaFuncAttributeMaxDynamicSharedMemorySize, SMEM_PIPE);
    cudaFuncSetAttribute(gemm_fp8<8>,   cudaFuncAttributeMaxDynamicSharedMemorySize, SMEM_PIPE8);
    cudaFuncSetAttribute(gemm_fp8<64>,  cudaFuncAttributeMaxDynamicSharedMemorySize, SMEM_PIPE8);
    cudaFuncSetAttribute(gemm_transadd, cudaFuncAttributeMaxDynamicSharedMemorySize, SMEM_PIPE);

    dim3 tb(32, 32);

    gn_stats<<<GROUPS, 512>>>(x);
    norm_transpose<<<dim3(PN / 32, CCH / 32), tb>>>(x, gamma, beta, hl);

    W4 ws = { { wq, wk, wv, wp } };
    wtrans4<<<dim3(16, 16, 4), tb>>>(ws, wt);

    // fused q/k/v projections: q,k -> fp8 row-major; v -> fp8 transposed (vt8)
    Ptr3 qkv = { bq, bk, bv, q8, k8, vt8 };
    gemm_qkv<<<dim3(CCH / BN, PN / BM, 3), 256, SMEM_PIPE>>>(hl, wt, CCH, qkv);

    const float scale = 0.044194173824159216f;  // 512^-0.5

    // scores: fp8 GEMM (K=512, fully unrolled), bf16 out, batched over 8 t-slices
    gemm_fp8<8><<<dim3(HWN / BN, HWN / BM, TT), 256, SMEM_PIPE8>>>(
        q8, k8, P, HWN, scale,
        (size_t)HWN * CCH, (size_t)HWN * CCH, (size_t)HWN * HWN);

    softmax8<<<TT * HWN, 256>>>(P, P8);

    // PV: fp8 GEMM (K=4096), o = (P8 @ vt8^T) / 256
    gemm_fp8<64><<<dim3(CCH / BN, HWN / BM, TT), 256, SMEM_PIPE8>>>(
        P8, vt8, o, CCH, 1.f / 256.f,
        (size_t)HWN * HWN, (size_t)CCH * HWN, (size_t)HWN * CCH);

    // output projection with fused transpose + residual (bf16)
    gemm_transadd<<<dim3(CCH / BN, PN / BM, 1), 256, SMEM_PIPE>>>(
        o, wt + 3 * CCH * CCH, bp, out, x);
}